// round 5
// baseline (speedup 1.0000x reference)
#include <cuda_runtime.h>
#include <cuda_fp16.h>
#include <math.h>
#include <stdint.h>

#define H 192
#define H3 576
#define MAXB 200000
#define EPSLN 1e-5f
#define AST 400   // layer A smem row stride bytes (200 halves)
#define WST 144   // W / head-A smem row stride bytes (72 halves)

// ===== device scratch =====
__device__ int   g_first[MAXB + 1];
__device__ float g_dist[MAXB];
__device__ float g_h[2 * (size_t)MAXB * H];
__device__ __half g_Whi[5 * H * H];
__device__ __half g_Wlo[5 * H * H];
__device__ __half g_W1hi[H * H3];
__device__ __half g_W1lo[H * H3];

// ===== helpers =====
__device__ __forceinline__ uint32_t smem_u32(const void* p) {
    uint32_t a;
    asm("{ .reg .u64 t; cvta.to.shared.u64 t, %1; cvt.u32.u64 %0, t; }" : "=r"(a) : "l"(p));
    return a;
}
__device__ __forceinline__ void ldsm4(uint32_t* r, uint32_t addr) {
    asm volatile("ldmatrix.sync.aligned.m8n8.x4.shared.b16 {%0,%1,%2,%3}, [%4];"
        : "=r"(r[0]), "=r"(r[1]), "=r"(r[2]), "=r"(r[3]) : "r"(addr));
}
__device__ __forceinline__ void mma_f16(float* c, const uint32_t* a, const uint32_t* b) {
    asm volatile("mma.sync.aligned.m16n8k16.row.col.f32.f16.f16.f32 "
        "{%0,%1,%2,%3}, {%4,%5,%6,%7}, {%8,%9}, {%0,%1,%2,%3};"
        : "+f"(c[0]), "+f"(c[1]), "+f"(c[2]), "+f"(c[3])
        : "r"(a[0]), "r"(a[1]), "r"(a[2]), "r"(a[3]), "r"(b[0]), "r"(b[1]));
}
__device__ __forceinline__ void cp16(uint32_t d, const void* s) {
    asm volatile("cp.async.cg.shared.global [%0], [%1], 16;" :: "r"(d), "l"(s));
}
#define CP_COMMIT() asm volatile("cp.async.commit_group;" ::: "memory")
#define CP_WAIT0()  asm volatile("cp.async.wait_group 0;" ::: "memory")

__device__ __forceinline__ void hsplit(float x, __half& hi, __half& lo) {
    hi = __float2half_rn(x);
    lo = __float2half_rn(x - __half2float(hi));
}

// ===== prep =====
__global__ __launch_bounds__(256)
void findfirst_kernel(const int* __restrict__ batch, int N, int B) {
    int i = blockIdx.x * blockDim.x + threadIdx.x;
    if (i == 0) g_first[B] = N;
    if (i >= N) return;
    if (i == 0 || batch[i] != batch[i - 1]) g_first[batch[i]] = i;
}

__global__ __launch_bounds__(256)
void dist_kernel(const float* __restrict__ pos, int B) {
    int m = blockIdx.x * blockDim.x + threadIdx.x;
    if (m >= B) return;
    int f = g_first[m], nf = g_first[m + 1];
    float d = 0.f;
    if (nf - f > 1) {
        int s = f + 1;
        float dx = pos[3*f+0]-pos[3*s+0], dy = pos[3*f+1]-pos[3*s+1], dz = pos[3*f+2]-pos[3*s+2];
        d = sqrtf(dx*dx + dy*dy + dz*dz + 1e-12f);
    }
    g_dist[m] = d;
}

__global__ __launch_bounds__(256)
void convw_kernel(const float* __restrict__ lW, const float* __restrict__ hW1, int L) {
    int idx = blockIdx.x * blockDim.x + threadIdx.x;
    int nlw = L * H * H;
    if (idx >= nlw + H * H3) return;
    __half hi, lo;
    if (idx < nlw) { hsplit(lW[idx], hi, lo); g_Whi[idx] = hi; g_Wlo[idx] = lo; }
    else { int j = idx - nlw; hsplit(hW1[j], hi, lo); g_W1hi[j] = hi; g_W1lo[j] = lo; }
}

// =====================================================================
// Layer: h <- h + relu(LN(h @ W^T + b)*g + beta)
// Block 512 thr, tile M=128 x N=192; warps 4(M)x4(N), warp tile 32x48.
// 3-MMA compensated fp16: Ahi*Whi + Ahi*Wlo + Alo*Whi.
// smem: Ahi 51200 | Alo 51200 | Whi 27648 | Wlo 27648 | prm 2304 | ps 2048 | pq 2048
// =====================================================================
#define L_ALO 51200
#define L_W   102400
#define L_WLO 27648
#define L_PRM 157696
#define L_PS  160000
#define L_PQ  162048
#define L_SMEM 164096

__global__ __launch_bounds__(512, 1)
void layer_mm_kernel(int l, int first, const int* __restrict__ z,
                     const float* __restrict__ emb,
                     const float* __restrict__ bias, const float* __restrict__ gamma,
                     const float* __restrict__ beta, int nrows, int B)
{
    extern __shared__ __align__(128) char sm[];
    const uint32_t sb = smem_u32(sm);
    __half* Ahi = (__half*)sm;
    __half* Alo = (__half*)(sm + L_ALO);
    float* prm = (float*)(sm + L_PRM);
    float* ps  = (float*)(sm + L_PS);
    float* pq  = (float*)(sm + L_PQ);

    const int tid = threadIdx.x, wid = tid >> 5, lane = tid & 31;
    const int row0 = blockIdx.x * 128;
    const __half* whi = g_Whi + (size_t)l * H * H;
    const __half* wlo = g_Wlo + (size_t)l * H * H;

    for (int e = tid; e < 576; e += 512)
        prm[e] = (e < 192) ? bias[e] : (e < 384) ? gamma[e - 192] : beta[e - 384];

    // stage A (128 rows, full K=192), fp32 -> fp16 hi/lo
    for (int u = tid; u < 128 * 48; u += 512) {
        int r = u / 48, t = u - r * 48;
        float4 v = make_float4(0.f, 0.f, 0.f, 0.f);
        int row = row0 + r;
        if (row < nrows) {
            if (first) {
                int m = (row < B) ? row : row - B;
                int f = g_first[m];
                int atom = (row >= B && (g_first[m + 1] - f) > 1) ? f + 1 : f;
                v = *(const float4*)(emb + (size_t)z[atom] * H + t * 4);
            } else {
                v = *(const float4*)(g_h + (size_t)row * H + t * 4);
            }
        }
        __half h0,h1,h2,h3,l0,l1,l2,l3;
        hsplit(v.x,h0,l0); hsplit(v.y,h1,l1); hsplit(v.z,h2,l2); hsplit(v.w,h3,l3);
        __half2* dh = (__half2*)(Ahi + r * 200 + t * 4);
        __half2* dl = (__half2*)(Alo + r * 200 + t * 4);
        dh[0] = __halves2half2(h0,h1); dh[1] = __halves2half2(h2,h3);
        dl[0] = __halves2half2(l0,l1); dl[1] = __halves2half2(l2,l3);
    }

    const int wm = (wid & 3) * 32, wn = (wid >> 2) * 48;
    float acc[2][6][4];
#pragma unroll
    for (int mi = 0; mi < 2; mi++)
#pragma unroll
        for (int ni = 0; ni < 6; ni++)
#pragma unroll
            for (int j = 0; j < 4; j++) acc[mi][ni][j] = 0.f;

    const int lr = lane & 15, lk = (lane >> 4) << 3;
    const int bn = (lane & 7) + ((lane >> 4) << 3), bk = ((lane >> 3) & 1) << 3;

    for (int c = 0; c < 3; c++) {
        __syncthreads();   // W buffer reuse + (c==0) A staging
        // stage W chunk c: hi and lo
        for (int u = tid; u < 3072; u += 512) {
            int e = (u < 1536) ? u : u - 1536;
            int n = e >> 3, seg = e & 7;
            const __half* src = ((u < 1536) ? whi : wlo) + (size_t)n * H + c * 64 + seg * 8;
            uint32_t dst = sb + L_W + ((u < 1536) ? 0u : (uint32_t)L_WLO) + n * WST + seg * 16;
            cp16(dst, src);
        }
        CP_COMMIT(); CP_WAIT0();
        __syncthreads();
#pragma unroll
        for (int s = 0; s < 4; s++) {
            const int k = c * 64 + s * 16, kl = s * 16;
            uint32_t ah[2][4], al[2][4];
            ldsm4(ah[0], sb + (wm +      lr) * AST + (k + lk) * 2);
            ldsm4(ah[1], sb + (wm + 16 + lr) * AST + (k + lk) * 2);
            ldsm4(al[0], sb + L_ALO + (wm +      lr) * AST + (k + lk) * 2);
            ldsm4(al[1], sb + L_ALO + (wm + 16 + lr) * AST + (k + lk) * 2);
            uint32_t bh[6][2], bl[6][2];
#pragma unroll
            for (int p = 0; p < 3; p++) {
                uint32_t q[4];
                ldsm4(q, sb + L_W + (wn + p * 16 + bn) * WST + (kl + bk) * 2);
                bh[2*p][0] = q[0]; bh[2*p][1] = q[1];
                bh[2*p+1][0] = q[2]; bh[2*p+1][1] = q[3];
                ldsm4(q, sb + L_W + L_WLO + (wn + p * 16 + bn) * WST + (kl + bk) * 2);
                bl[2*p][0] = q[0]; bl[2*p][1] = q[1];
                bl[2*p+1][0] = q[2]; bl[2*p+1][1] = q[3];
            }
#pragma unroll
            for (int mi = 0; mi < 2; mi++)
#pragma unroll
                for (int ni = 0; ni < 6; ni++) {
                    mma_f16(acc[mi][ni], ah[mi], bh[ni]);
                    mma_f16(acc[mi][ni], ah[mi], bl[ni]);
                    mma_f16(acc[mi][ni], al[mi], bh[ni]);
                }
        }
    }

    // ===== epilogue: bias + LN stats =====
    const int c4 = lane & 3, lr4 = lane >> 2, wnIdx = wid >> 2;
    float sv[2][2] = {{0,0},{0,0}}, qv[2][2] = {{0,0},{0,0}};
#pragma unroll
    for (int mi = 0; mi < 2; mi++)
#pragma unroll
        for (int ni = 0; ni < 6; ni++) {
            int col = wn + 8 * ni + 2 * c4;
            float b0 = prm[col], b1 = prm[col + 1];
            acc[mi][ni][0] += b0; acc[mi][ni][1] += b1;
            acc[mi][ni][2] += b0; acc[mi][ni][3] += b1;
            sv[mi][0] += acc[mi][ni][0] + acc[mi][ni][1];
            qv[mi][0] += acc[mi][ni][0]*acc[mi][ni][0] + acc[mi][ni][1]*acc[mi][ni][1];
            sv[mi][1] += acc[mi][ni][2] + acc[mi][ni][3];
            qv[mi][1] += acc[mi][ni][2]*acc[mi][ni][2] + acc[mi][ni][3]*acc[mi][ni][3];
        }
#pragma unroll
    for (int o = 1; o <= 2; o <<= 1)
#pragma unroll
        for (int mi = 0; mi < 2; mi++)
#pragma unroll
            for (int hf = 0; hf < 2; hf++) {
                sv[mi][hf] += __shfl_xor_sync(0xffffffffu, sv[mi][hf], o);
                qv[mi][hf] += __shfl_xor_sync(0xffffffffu, qv[mi][hf], o);
            }
    __syncthreads();   // mainloop reads of W/A done before ps/pq write? (ps/pq disjoint; sync for store->load order below)
    if (c4 == 0) {
#pragma unroll
        for (int mi = 0; mi < 2; mi++)
#pragma unroll
            for (int hf = 0; hf < 2; hf++) {
                int row = wm + 16 * mi + 8 * hf + lr4;
                ps[row * 4 + wnIdx] = sv[mi][hf];
                pq[row * 4 + wnIdx] = qv[mi][hf];
            }
    }
    __syncthreads();

    float mu[2][2], rs[2][2];
#pragma unroll
    for (int mi = 0; mi < 2; mi++)
#pragma unroll
        for (int hf = 0; hf < 2; hf++) {
            int row = wm + 16 * mi + 8 * hf + lr4;
            float s = ps[row*4] + ps[row*4+1] + ps[row*4+2] + ps[row*4+3];
            float q2 = pq[row*4] + pq[row*4+1] + pq[row*4+2] + pq[row*4+3];
            float m_ = s * (1.f / 192.f);
            float v_ = q2 * (1.f / 192.f) - m_ * m_;
            mu[mi][hf] = m_;
            rs[mi][hf] = rsqrtf(fmaxf(v_, 0.f) + EPSLN);
        }

    const float* pg = prm + 192;
    const float* pbt = prm + 384;
#pragma unroll
    for (int mi = 0; mi < 2; mi++) {
        int ra = wm + 16 * mi + lr4, rb = ra + 8;
        bool oka = (row0 + ra < nrows), okb = (row0 + rb < nrows);
#pragma unroll
        for (int ni = 0; ni < 6; ni++) {
            int col = wn + 8 * ni + 2 * c4;
            float g0 = pg[col], g1 = pg[col+1], t0 = pbt[col], t1 = pbt[col+1];
            if (oka) {
                float v0 = fmaxf((acc[mi][ni][0] - mu[mi][0]) * rs[mi][0] * g0 + t0, 0.f);
                float v1 = fmaxf((acc[mi][ni][1] - mu[mi][0]) * rs[mi][0] * g1 + t1, 0.f);
                __half2 oh = *(__half2*)(Ahi + ra * 200 + col);
                __half2 ol = *(__half2*)(Alo + ra * 200 + col);
                float2 o;
                o.x = __low2float(oh)  + __low2float(ol)  + v0;
                o.y = __high2float(oh) + __high2float(ol) + v1;
                *(float2*)(g_h + (size_t)(row0 + ra) * H + col) = o;
            }
            if (okb) {
                float v0 = fmaxf((acc[mi][ni][2] - mu[mi][1]) * rs[mi][1] * g0 + t0, 0.f);
                float v1 = fmaxf((acc[mi][ni][3] - mu[mi][1]) * rs[mi][1] * g1 + t1, 0.f);
                __half2 oh = *(__half2*)(Ahi + rb * 200 + col);
                __half2 ol = *(__half2*)(Alo + rb * 200 + col);
                float2 o;
                o.x = __low2float(oh)  + __low2float(ol)  + v0;
                o.y = __high2float(oh) + __high2float(ol) + v1;
                *(float2*)(g_h + (size_t)(row0 + rb) * H + col) = o;
            }
        }
    }
}

// =====================================================================
// Head: out = relu([h1|h2|distfeat] @ W1^T + b1) . W2 + b2
// Block 512 thr, M=128 tile; K=576 in 9 chunks; A and W double-buffered hi/lo.
// smem: A[2 x (hi 18432 + lo 18432)] = 73728 | W[2 x (hi 27648 + lo 27648)] = 110592
//       | prm 3072 | part 2048
// =====================================================================
#define HD_W    73728
#define HD_PRM  184320
#define HD_PART 187392
#define HD_SMEM 189440

__global__ __launch_bounds__(512, 1)
void head_mm_kernel(const float* __restrict__ b1, const float* __restrict__ W2,
                    const float* __restrict__ b2,
                    const float* __restrict__ dW, const float* __restrict__ dB,
                    float* __restrict__ out, int Bm)
{
    extern __shared__ __align__(128) char sm[];
    const uint32_t sb = smem_u32(sm);
    float* prm  = (float*)(sm + HD_PRM);   // b1 | W2 | dW | dB
    float* part = (float*)(sm + HD_PART);

    const int tid = threadIdx.x, wid = tid >> 5, lane = tid & 31;
    const int row0 = blockIdx.x * 128;

    // prefetch W1 chunk 0 (hi+lo) into W buffer 0
    for (int u = tid; u < 3072; u += 512) {
        int e = (u < 1536) ? u : u - 1536;
        int n = e >> 3, seg = e & 7;
        const __half* src = ((u < 1536) ? g_W1hi : g_W1lo) + (size_t)n * H3 + seg * 8;
        cp16(sb + HD_W + ((u < 1536) ? 0u : 27648u) + n * WST + seg * 16, src);
    }
    CP_COMMIT();

    for (int e = tid; e < 768; e += 512)
        prm[e] = (e < 192) ? b1[e] : (e < 384) ? W2[e-192] : (e < 576) ? dW[e-384] : dB[e-576];
    __syncthreads();   // prm (dW/dB) needed by A staging

    auto stageA = [&](int c, int b) {
        __half* Ahi = (__half*)(sm + b * 36864);
        __half* Alo = (__half*)(sm + b * 36864 + 18432);
        for (int u = tid; u < 128 * 16; u += 512) {
            int r = u >> 4, t = u & 15;
            int m = row0 + r;
            float4 v = make_float4(0.f, 0.f, 0.f, 0.f);
            if (m < Bm) {
                if (c < 3)      v = *(const float4*)(g_h + (size_t)m * H + c * 64 + t * 4);
                else if (c < 6) v = *(const float4*)(g_h + ((size_t)Bm + m) * H + (c - 3) * 64 + t * 4);
                else {
                    int k = (c - 6) * 64 + t * 4;
                    float d = g_dist[m];
                    v.x = d * prm[384 + k]     + prm[576 + k];
                    v.y = d * prm[384 + k + 1] + prm[576 + k + 1];
                    v.z = d * prm[384 + k + 2] + prm[576 + k + 2];
                    v.w = d * prm[384 + k + 3] + prm[576 + k + 3];
                }
            }
            __half h0,h1,h2,h3,l0,l1,l2,l3;
            hsplit(v.x,h0,l0); hsplit(v.y,h1,l1); hsplit(v.z,h2,l2); hsplit(v.w,h3,l3);
            __half2* dh = (__half2*)(Ahi + r * 72 + t * 4);
            __half2* dl = (__half2*)(Alo + r * 72 + t * 4);
            dh[0] = __halves2half2(h0,h1); dh[1] = __halves2half2(h2,h3);
            dl[0] = __halves2half2(l0,l1); dl[1] = __halves2half2(l2,l3);
        }
    };
    stageA(0, 0);

    const int wm = (wid & 3) * 32, wn = (wid >> 2) * 48;
    float acc[2][6][4];
#pragma unroll
    for (int mi = 0; mi < 2; mi++)
#pragma unroll
        for (int ni = 0; ni < 6; ni++)
#pragma unroll
            for (int j = 0; j < 4; j++) acc[mi][ni][j] = 0.f;

    const int lr = lane & 15, lk = (lane >> 4) << 3;
    const int bn = (lane & 7) + ((lane >> 4) << 3), bk = ((lane >> 3) & 1) << 3;

    CP_WAIT0();
    __syncthreads();

    for (int c = 0; c < 9; c++) {
        if (c < 8) {
            uint32_t nb = sb + HD_W + ((c + 1) & 1) * 55296u;
            for (int u = tid; u < 3072; u += 512) {
                int e = (u < 1536) ? u : u - 1536;
                int n = e >> 3, seg = e & 7;
                const __half* src = ((u < 1536) ? g_W1hi : g_W1lo)
                                    + (size_t)n * H3 + (c + 1) * 64 + seg * 8;
                cp16(nb + ((u < 1536) ? 0u : 27648u) + n * WST + seg * 16, src);
            }
            CP_COMMIT();
            stageA(c + 1, (c + 1) & 1);
        }
        uint32_t ab = sb + (c & 1) * 36864u;
        uint32_t wb = sb + HD_W + (c & 1) * 55296u;
#pragma unroll
        for (int s = 0; s < 4; s++) {
            const int kl = s * 16;
            uint32_t ah[2][4], al[2][4];
            ldsm4(ah[0], ab + (wm +      lr) * WST + (kl + lk) * 2);
            ldsm4(ah[1], ab + (wm + 16 + lr) * WST + (kl + lk) * 2);
            ldsm4(al[0], ab + 18432 + (wm +      lr) * WST + (kl + lk) * 2);
            ldsm4(al[1], ab + 18432 + (wm + 16 + lr) * WST + (kl + lk) * 2);
            uint32_t bh[6][2], bl[6][2];
#pragma unroll
            for (int p = 0; p < 3; p++) {
                uint32_t q[4];
                ldsm4(q, wb + (wn + p * 16 + bn) * WST + (kl + bk) * 2);
                bh[2*p][0] = q[0]; bh[2*p][1] = q[1];
                bh[2*p+1][0] = q[2]; bh[2*p+1][1] = q[3];
                ldsm4(q, wb + 27648 + (wn + p * 16 + bn) * WST + (kl + bk) * 2);
                bl[2*p][0] = q[0]; bl[2*p][1] = q[1];
                bl[2*p+1][0] = q[2]; bl[2*p+1][1] = q[3];
            }
#pragma unroll
            for (int mi = 0; mi < 2; mi++)
#pragma unroll
                for (int ni = 0; ni < 6; ni++) {
                    mma_f16(acc[mi][ni], ah[mi], bh[ni]);
                    mma_f16(acc[mi][ni], ah[mi], bl[ni]);
                    mma_f16(acc[mi][ni], al[mi], bh[ni]);
                }
        }
        if (c < 8) { CP_WAIT0(); __syncthreads(); }
    }

    // epilogue: relu(y+b1) . W2
    const int c4 = lane & 3, lr4 = lane >> 2, wnIdx = wid >> 2;
    float pv[2][2] = {{0,0},{0,0}};
#pragma unroll
    for (int mi = 0; mi < 2; mi++)
#pragma unroll
        for (int ni = 0; ni < 6; ni++) {
            int col = wn + 8 * ni + 2 * c4;
            float b0 = prm[col], b1v = prm[col + 1];
            float w0 = prm[192 + col], w1 = prm[192 + col + 1];
            pv[mi][0] += fmaxf(acc[mi][ni][0] + b0, 0.f) * w0 + fmaxf(acc[mi][ni][1] + b1v, 0.f) * w1;
            pv[mi][1] += fmaxf(acc[mi][ni][2] + b0, 0.f) * w0 + fmaxf(acc[mi][ni][3] + b1v, 0.f) * w1;
        }
#pragma unroll
    for (int o = 1; o <= 2; o <<= 1)
#pragma unroll
        for (int mi = 0; mi < 2; mi++)
#pragma unroll
            for (int hf = 0; hf < 2; hf++)
                pv[mi][hf] += __shfl_xor_sync(0xffffffffu, pv[mi][hf], o);
    __syncthreads();
    if (c4 == 0) {
#pragma unroll
        for (int mi = 0; mi < 2; mi++)
#pragma unroll
            for (int hf = 0; hf < 2; hf++) {
                int row = wm + 16 * mi + 8 * hf + lr4;
                part[row * 4 + wnIdx] = pv[mi][hf];
            }
    }
    __syncthreads();
    if (tid < 128 && row0 + tid < Bm) {
        out[row0 + tid] = part[tid*4] + part[tid*4+1] + part[tid*4+2] + part[tid*4+3] + b2[0];
    }
}

// ===== launch =====
extern "C" void kernel_launch(void* const* d_in, const int* in_sizes, int n_in,
                              void* d_out, int out_size)
{
    const int*   z        = (const int*)  d_in[1];
    const float* pos      = (const float*)d_in[2];
    const int*   batch    = (const int*)  d_in[3];
    const float* emb      = (const float*)d_in[5];
    const float* layer_W  = (const float*)d_in[6];
    const float* layer_b  = (const float*)d_in[7];
    const float* layer_g  = (const float*)d_in[8];
    const float* layer_bt = (const float*)d_in[9];
    const float* dist_W   = (const float*)d_in[10];
    const float* dist_b   = (const float*)d_in[11];
    const float* head_W1  = (const float*)d_in[12];
    const float* head_b1  = (const float*)d_in[13];
    const float* head_W2  = (const float*)d_in[14];
    const float* head_b2  = (const float*)d_in[15];
    float* out = (float*)d_out;

    const int B = out_size;
    const int N = in_sizes[1];
    const int L = in_sizes[6] / (H * H);
    const int nrows = 2 * B;

    cudaFuncSetAttribute(layer_mm_kernel, cudaFuncAttributeMaxDynamicSharedMemorySize, L_SMEM);
    cudaFuncSetAttribute(head_mm_kernel,  cudaFuncAttributeMaxDynamicSharedMemorySize, HD_SMEM);

    findfirst_kernel<<<(N + 255) / 256, 256>>>(batch, N, B);
    dist_kernel<<<(B + 255) / 256, 256>>>(pos, B);
    convw_kernel<<<(L * H * H + H * H3 + 255) / 256, 256>>>(layer_W, head_W1, L);

    for (int l = 0; l < L; l++) {
        layer_mm_kernel<<<(nrows + 127) / 128, 512, L_SMEM>>>(
            l, (l == 0) ? 1 : 0, z, emb,
            layer_b + l * H, layer_g + l * H, layer_bt + l * H, nrows, B);
    }
    head_mm_kernel<<<(B + 127) / 128, 512, HD_SMEM>>>(
        head_b1, head_W2, head_b2, dist_W, dist_b, out, B);
}

// round 6
// speedup vs baseline: 1.0317x; 1.0317x over previous
#include <cuda_runtime.h>
#include <cuda_fp16.h>
#include <math.h>
#include <stdint.h>

#define H 192
#define H3 576
#define MAXB 200000
#define EPSLN 1e-5f
#define AST 400   // layer A smem row stride bytes (200 halves)
#define WST 144   // W / head-A smem row stride bytes (72 halves)

// ===== device scratch =====
__device__ int   g_first[MAXB + 1];
__device__ float g_dist[MAXB];
__device__ float g_h[2 * (size_t)MAXB * H];
__device__ __half g_Whi[5 * H * H];
__device__ __half g_Wlo[5 * H * H];
__device__ __half g_W1hi[H * H3];
__device__ __half g_W1lo[H * H3];

// ===== helpers =====
__device__ __forceinline__ uint32_t smem_u32(const void* p) {
    uint32_t a;
    asm("{ .reg .u64 t; cvta.to.shared.u64 t, %1; cvt.u32.u64 %0, t; }" : "=r"(a) : "l"(p));
    return a;
}
__device__ __forceinline__ void ldsm4(uint32_t* r, uint32_t addr) {
    asm volatile("ldmatrix.sync.aligned.m8n8.x4.shared.b16 {%0,%1,%2,%3}, [%4];"
        : "=r"(r[0]), "=r"(r[1]), "=r"(r[2]), "=r"(r[3]) : "r"(addr));
}
__device__ __forceinline__ void mma_f16(float* c, const uint32_t* a, const uint32_t* b) {
    asm volatile("mma.sync.aligned.m16n8k16.row.col.f32.f16.f16.f32 "
        "{%0,%1,%2,%3}, {%4,%5,%6,%7}, {%8,%9}, {%0,%1,%2,%3};"
        : "+f"(c[0]), "+f"(c[1]), "+f"(c[2]), "+f"(c[3])
        : "r"(a[0]), "r"(a[1]), "r"(a[2]), "r"(a[3]), "r"(b[0]), "r"(b[1]));
}
__device__ __forceinline__ void cp16(uint32_t d, const void* s) {
    asm volatile("cp.async.cg.shared.global [%0], [%1], 16;" :: "r"(d), "l"(s));
}
#define CP_COMMIT() asm volatile("cp.async.commit_group;" ::: "memory")
#define CP_WAIT0()  asm volatile("cp.async.wait_group 0;" ::: "memory")

__device__ __forceinline__ void hsplit(float x, __half& hi, __half& lo) {
    hi = __float2half_rn(x);
    lo = __float2half_rn(x - __half2float(hi));
}

// ===== prep =====
__global__ __launch_bounds__(256)
void findfirst_kernel(const int* __restrict__ batch, int N, int B) {
    int i = blockIdx.x * blockDim.x + threadIdx.x;
    if (i == 0) g_first[B] = N;
    if (i >= N) return;
    if (i == 0 || batch[i] != batch[i - 1]) g_first[batch[i]] = i;
}

__global__ __launch_bounds__(256)
void dist_kernel(const float* __restrict__ pos, int B) {
    int m = blockIdx.x * blockDim.x + threadIdx.x;
    if (m >= B) return;
    int f = g_first[m], nf = g_first[m + 1];
    float d = 0.f;
    if (nf - f > 1) {
        int s = f + 1;
        float dx = pos[3*f+0]-pos[3*s+0], dy = pos[3*f+1]-pos[3*s+1], dz = pos[3*f+2]-pos[3*s+2];
        d = sqrtf(dx*dx + dy*dy + dz*dz + 1e-12f);
    }
    g_dist[m] = d;
}

__global__ __launch_bounds__(256)
void convw_kernel(const float* __restrict__ lW, const float* __restrict__ hW1, int L) {
    int idx = blockIdx.x * blockDim.x + threadIdx.x;
    int nlw = L * H * H;
    if (idx >= nlw + H * H3) return;
    __half hi, lo;
    if (idx < nlw) { hsplit(lW[idx], hi, lo); g_Whi[idx] = hi; g_Wlo[idx] = lo; }
    else { int j = idx - nlw; hsplit(hW1[j], hi, lo); g_W1hi[j] = hi; g_W1lo[j] = lo; }
}

// =====================================================================
// Layer: h <- h + relu(LN(h @ W^T + b)*g + beta)
// Block 512 thr, tile M=128 x N=192; warps 4(M)x4(N), warp tile 32x48.
// 3-MMA compensated fp16: Ahi*Whi + Ahi*Wlo + Alo*Whi.
// W hi+lo DOUBLE-BUFFERED via cp.async; one __syncthreads per chunk.
// smem: Ahi 51200 | Alo 51200 | W 2x(27648+27648)=110592 | prm 2304 | ps 2048 | pq 2048
// =====================================================================
#define L_ALO 51200
#define L_W   102400
#define L_WLO 27648
#define L_WBUF 55296
#define L_PRM 212992
#define L_PS  215296
#define L_PQ  217344
#define L_SMEM 219392

__global__ __launch_bounds__(512, 1)
void layer_mm_kernel(int l, int first, const int* __restrict__ z,
                     const float* __restrict__ emb,
                     const float* __restrict__ bias, const float* __restrict__ gamma,
                     const float* __restrict__ beta, int nrows, int B)
{
    extern __shared__ __align__(128) char sm[];
    const uint32_t sb = smem_u32(sm);
    __half* Ahi = (__half*)sm;
    __half* Alo = (__half*)(sm + L_ALO);
    float* prm = (float*)(sm + L_PRM);
    float* ps  = (float*)(sm + L_PS);
    float* pq  = (float*)(sm + L_PQ);

    const int tid = threadIdx.x, wid = tid >> 5, lane = tid & 31;
    const int row0 = blockIdx.x * 128;
    const __half* whi = g_Whi + (size_t)l * H * H;
    const __half* wlo = g_Wlo + (size_t)l * H * H;

    // prefetch W chunk 0 (hi+lo) into buffer 0
    for (int u = tid; u < 3072; u += 512) {
        int e = (u < 1536) ? u : u - 1536;
        int n = e >> 3, seg = e & 7;
        const __half* src = ((u < 1536) ? whi : wlo) + (size_t)n * H + seg * 8;
        cp16(sb + L_W + ((u < 1536) ? 0u : (uint32_t)L_WLO) + n * WST + seg * 16, src);
    }
    CP_COMMIT();

    for (int e = tid; e < 576; e += 512)
        prm[e] = (e < 192) ? bias[e] : (e < 384) ? gamma[e - 192] : beta[e - 384];

    // stage A (128 rows, full K=192), fp32 -> fp16 hi/lo (overlaps W chunk0 load)
    for (int u = tid; u < 128 * 48; u += 512) {
        int r = u / 48, t = u - r * 48;
        float4 v = make_float4(0.f, 0.f, 0.f, 0.f);
        int row = row0 + r;
        if (row < nrows) {
            if (first) {
                int m = (row < B) ? row : row - B;
                int f = g_first[m];
                int atom = (row >= B && (g_first[m + 1] - f) > 1) ? f + 1 : f;
                v = *(const float4*)(emb + (size_t)z[atom] * H + t * 4);
            } else {
                v = *(const float4*)(g_h + (size_t)row * H + t * 4);
            }
        }
        __half h0,h1,h2,h3,l0,l1,l2,l3;
        hsplit(v.x,h0,l0); hsplit(v.y,h1,l1); hsplit(v.z,h2,l2); hsplit(v.w,h3,l3);
        __half2* dh = (__half2*)(Ahi + r * 200 + t * 4);
        __half2* dl = (__half2*)(Alo + r * 200 + t * 4);
        dh[0] = __halves2half2(h0,h1); dh[1] = __halves2half2(h2,h3);
        dl[0] = __halves2half2(l0,l1); dl[1] = __halves2half2(l2,l3);
    }

    const int wm = (wid & 3) * 32, wn = (wid >> 2) * 48;
    float acc[2][6][4];
#pragma unroll
    for (int mi = 0; mi < 2; mi++)
#pragma unroll
        for (int ni = 0; ni < 6; ni++)
#pragma unroll
            for (int j = 0; j < 4; j++) acc[mi][ni][j] = 0.f;

    const int lr = lane & 15, lk = (lane >> 4) << 3;
    const int bn = (lane & 7) + ((lane >> 4) << 3), bk = ((lane >> 3) & 1) << 3;

    for (int c = 0; c < 3; c++) {
        CP_WAIT0();          // chunk c ready (its group is the only one pending)
        __syncthreads();     // all warps done with chunk c-1 (safe to overwrite buf (c+1)&1)
        if (c < 2) {
            uint32_t nb = sb + L_W + (uint32_t)((c + 1) & 1) * L_WBUF;
            for (int u = tid; u < 3072; u += 512) {
                int e = (u < 1536) ? u : u - 1536;
                int n = e >> 3, seg = e & 7;
                const __half* src = ((u < 1536) ? whi : wlo) + (size_t)n * H + (c + 1) * 64 + seg * 8;
                cp16(nb + ((u < 1536) ? 0u : (uint32_t)L_WLO) + n * WST + seg * 16, src);
            }
            CP_COMMIT();     // overlaps compute of chunk c below
        }
        uint32_t wb = sb + L_W + (uint32_t)(c & 1) * L_WBUF;
#pragma unroll
        for (int s = 0; s < 4; s++) {
            const int k = c * 64 + s * 16, kl = s * 16;
            uint32_t ah[2][4], al[2][4];
            ldsm4(ah[0], sb + (wm +      lr) * AST + (k + lk) * 2);
            ldsm4(ah[1], sb + (wm + 16 + lr) * AST + (k + lk) * 2);
            ldsm4(al[0], sb + L_ALO + (wm +      lr) * AST + (k + lk) * 2);
            ldsm4(al[1], sb + L_ALO + (wm + 16 + lr) * AST + (k + lk) * 2);
            uint32_t bh[6][2], bl[6][2];
#pragma unroll
            for (int p = 0; p < 3; p++) {
                uint32_t q[4];
                ldsm4(q, wb + (wn + p * 16 + bn) * WST + (kl + bk) * 2);
                bh[2*p][0] = q[0]; bh[2*p][1] = q[1];
                bh[2*p+1][0] = q[2]; bh[2*p+1][1] = q[3];
                ldsm4(q, wb + L_WLO + (wn + p * 16 + bn) * WST + (kl + bk) * 2);
                bl[2*p][0] = q[0]; bl[2*p][1] = q[1];
                bl[2*p+1][0] = q[2]; bl[2*p+1][1] = q[3];
            }
#pragma unroll
            for (int mi = 0; mi < 2; mi++)
#pragma unroll
                for (int ni = 0; ni < 6; ni++) {
                    mma_f16(acc[mi][ni], ah[mi], bh[ni]);
                    mma_f16(acc[mi][ni], ah[mi], bl[ni]);
                    mma_f16(acc[mi][ni], al[mi], bh[ni]);
                }
        }
    }

    // ===== epilogue: bias + LN stats =====
    const int c4 = lane & 3, lr4 = lane >> 2, wnIdx = wid >> 2;
    float sv[2][2] = {{0,0},{0,0}}, qv[2][2] = {{0,0},{0,0}};
#pragma unroll
    for (int mi = 0; mi < 2; mi++)
#pragma unroll
        for (int ni = 0; ni < 6; ni++) {
            int col = wn + 8 * ni + 2 * c4;
            float b0 = prm[col], b1 = prm[col + 1];
            acc[mi][ni][0] += b0; acc[mi][ni][1] += b1;
            acc[mi][ni][2] += b0; acc[mi][ni][3] += b1;
            sv[mi][0] += acc[mi][ni][0] + acc[mi][ni][1];
            qv[mi][0] += acc[mi][ni][0]*acc[mi][ni][0] + acc[mi][ni][1]*acc[mi][ni][1];
            sv[mi][1] += acc[mi][ni][2] + acc[mi][ni][3];
            qv[mi][1] += acc[mi][ni][2]*acc[mi][ni][2] + acc[mi][ni][3]*acc[mi][ni][3];
        }
#pragma unroll
    for (int o = 1; o <= 2; o <<= 1)
#pragma unroll
        for (int mi = 0; mi < 2; mi++)
#pragma unroll
            for (int hf = 0; hf < 2; hf++) {
                sv[mi][hf] += __shfl_xor_sync(0xffffffffu, sv[mi][hf], o);
                qv[mi][hf] += __shfl_xor_sync(0xffffffffu, qv[mi][hf], o);
            }
    if (c4 == 0) {
#pragma unroll
        for (int mi = 0; mi < 2; mi++)
#pragma unroll
            for (int hf = 0; hf < 2; hf++) {
                int row = wm + 16 * mi + 8 * hf + lr4;
                ps[row * 4 + wnIdx] = sv[mi][hf];
                pq[row * 4 + wnIdx] = qv[mi][hf];
            }
    }
    __syncthreads();

    float mu[2][2], rs[2][2];
#pragma unroll
    for (int mi = 0; mi < 2; mi++)
#pragma unroll
        for (int hf = 0; hf < 2; hf++) {
            int row = wm + 16 * mi + 8 * hf + lr4;
            float s = ps[row*4] + ps[row*4+1] + ps[row*4+2] + ps[row*4+3];
            float q2 = pq[row*4] + pq[row*4+1] + pq[row*4+2] + pq[row*4+3];
            float m_ = s * (1.f / 192.f);
            float v_ = q2 * (1.f / 192.f) - m_ * m_;
            mu[mi][hf] = m_;
            rs[mi][hf] = rsqrtf(fmaxf(v_, 0.f) + EPSLN);
        }

    const float* pg = prm + 192;
    const float* pbt = prm + 384;
#pragma unroll
    for (int mi = 0; mi < 2; mi++) {
        int ra = wm + 16 * mi + lr4, rb = ra + 8;
        bool oka = (row0 + ra < nrows), okb = (row0 + rb < nrows);
#pragma unroll
        for (int ni = 0; ni < 6; ni++) {
            int col = wn + 8 * ni + 2 * c4;
            float g0 = pg[col], g1 = pg[col+1], t0 = pbt[col], t1 = pbt[col+1];
            if (oka) {
                float v0 = fmaxf((acc[mi][ni][0] - mu[mi][0]) * rs[mi][0] * g0 + t0, 0.f);
                float v1 = fmaxf((acc[mi][ni][1] - mu[mi][0]) * rs[mi][0] * g1 + t1, 0.f);
                __half2 oh = *(__half2*)(Ahi + ra * 200 + col);
                __half2 ol = *(__half2*)(Alo + ra * 200 + col);
                float2 o;
                o.x = __low2float(oh)  + __low2float(ol)  + v0;
                o.y = __high2float(oh) + __high2float(ol) + v1;
                *(float2*)(g_h + (size_t)(row0 + ra) * H + col) = o;
            }
            if (okb) {
                float v0 = fmaxf((acc[mi][ni][2] - mu[mi][1]) * rs[mi][1] * g0 + t0, 0.f);
                float v1 = fmaxf((acc[mi][ni][3] - mu[mi][1]) * rs[mi][1] * g1 + t1, 0.f);
                __half2 oh = *(__half2*)(Ahi + rb * 200 + col);
                __half2 ol = *(__half2*)(Alo + rb * 200 + col);
                float2 o;
                o.x = __low2float(oh)  + __low2float(ol)  + v0;
                o.y = __high2float(oh) + __high2float(ol) + v1;
                *(float2*)(g_h + (size_t)(row0 + rb) * H + col) = o;
            }
        }
    }
}

// =====================================================================
// Head: out = relu([h1|h2|distfeat] @ W1^T + b1) . W2 + b2
// Block 512 thr, M=128 tile; K=576 in 9 chunks; A and W double-buffered hi/lo.
// =====================================================================
#define HD_W    73728
#define HD_PRM  184320
#define HD_PART 187392
#define HD_SMEM 189440

__global__ __launch_bounds__(512, 1)
void head_mm_kernel(const float* __restrict__ b1, const float* __restrict__ W2,
                    const float* __restrict__ b2,
                    const float* __restrict__ dW, const float* __restrict__ dB,
                    float* __restrict__ out, int Bm)
{
    extern __shared__ __align__(128) char sm[];
    const uint32_t sb = smem_u32(sm);
    float* prm  = (float*)(sm + HD_PRM);   // b1 | W2 | dW | dB
    float* part = (float*)(sm + HD_PART);

    const int tid = threadIdx.x, wid = tid >> 5, lane = tid & 31;
    const int row0 = blockIdx.x * 128;

    for (int u = tid; u < 3072; u += 512) {
        int e = (u < 1536) ? u : u - 1536;
        int n = e >> 3, seg = e & 7;
        const __half* src = ((u < 1536) ? g_W1hi : g_W1lo) + (size_t)n * H3 + seg * 8;
        cp16(sb + HD_W + ((u < 1536) ? 0u : 27648u) + n * WST + seg * 16, src);
    }
    CP_COMMIT();

    for (int e = tid; e < 768; e += 512)
        prm[e] = (e < 192) ? b1[e] : (e < 384) ? W2[e-192] : (e < 576) ? dW[e-384] : dB[e-576];
    __syncthreads();

    auto stageA = [&](int c, int b) {
        __half* Ahi = (__half*)(sm + b * 36864);
        __half* Alo = (__half*)(sm + b * 36864 + 18432);
        for (int u = tid; u < 128 * 16; u += 512) {
            int r = u >> 4, t = u & 15;
            int m = row0 + r;
            float4 v = make_float4(0.f, 0.f, 0.f, 0.f);
            if (m < Bm) {
                if (c < 3)      v = *(const float4*)(g_h + (size_t)m * H + c * 64 + t * 4);
                else if (c < 6) v = *(const float4*)(g_h + ((size_t)Bm + m) * H + (c - 3) * 64 + t * 4);
                else {
                    int k = (c - 6) * 64 + t * 4;
                    float d = g_dist[m];
                    v.x = d * prm[384 + k]     + prm[576 + k];
                    v.y = d * prm[384 + k + 1] + prm[576 + k + 1];
                    v.z = d * prm[384 + k + 2] + prm[576 + k + 2];
                    v.w = d * prm[384 + k + 3] + prm[576 + k + 3];
                }
            }
            __half h0,h1,h2,h3,l0,l1,l2,l3;
            hsplit(v.x,h0,l0); hsplit(v.y,h1,l1); hsplit(v.z,h2,l2); hsplit(v.w,h3,l3);
            __half2* dh = (__half2*)(Ahi + r * 72 + t * 4);
            __half2* dl = (__half2*)(Alo + r * 72 + t * 4);
            dh[0] = __halves2half2(h0,h1); dh[1] = __halves2half2(h2,h3);
            dl[0] = __halves2half2(l0,l1); dl[1] = __halves2half2(l2,l3);
        }
    };
    stageA(0, 0);

    const int wm = (wid & 3) * 32, wn = (wid >> 2) * 48;
    float acc[2][6][4];
#pragma unroll
    for (int mi = 0; mi < 2; mi++)
#pragma unroll
        for (int ni = 0; ni < 6; ni++)
#pragma unroll
            for (int j = 0; j < 4; j++) acc[mi][ni][j] = 0.f;

    const int lr = lane & 15, lk = (lane >> 4) << 3;
    const int bn = (lane & 7) + ((lane >> 4) << 3), bk = ((lane >> 3) & 1) << 3;

    CP_WAIT0();
    __syncthreads();

    for (int c = 0; c < 9; c++) {
        if (c < 8) {
            uint32_t nb = sb + HD_W + ((c + 1) & 1) * 55296u;
            for (int u = tid; u < 3072; u += 512) {
                int e = (u < 1536) ? u : u - 1536;
                int n = e >> 3, seg = e & 7;
                const __half* src = ((u < 1536) ? g_W1hi : g_W1lo)
                                    + (size_t)n * H3 + (c + 1) * 64 + seg * 8;
                cp16(nb + ((u < 1536) ? 0u : 27648u) + n * WST + seg * 16, src);
            }
            CP_COMMIT();
            stageA(c + 1, (c + 1) & 1);
        }
        uint32_t ab = sb + (c & 1) * 36864u;
        uint32_t wb = sb + HD_W + (c & 1) * 55296u;
#pragma unroll
        for (int s = 0; s < 4; s++) {
            const int kl = s * 16;
            uint32_t ah[2][4], al[2][4];
            ldsm4(ah[0], ab + (wm +      lr) * WST + (kl + lk) * 2);
            ldsm4(ah[1], ab + (wm + 16 + lr) * WST + (kl + lk) * 2);
            ldsm4(al[0], ab + 18432 + (wm +      lr) * WST + (kl + lk) * 2);
            ldsm4(al[1], ab + 18432 + (wm + 16 + lr) * WST + (kl + lk) * 2);
            uint32_t bh[6][2], bl[6][2];
#pragma unroll
            for (int p = 0; p < 3; p++) {
                uint32_t q[4];
                ldsm4(q, wb + (wn + p * 16 + bn) * WST + (kl + bk) * 2);
                bh[2*p][0] = q[0]; bh[2*p][1] = q[1];
                bh[2*p+1][0] = q[2]; bh[2*p+1][1] = q[3];
                ldsm4(q, wb + 27648 + (wn + p * 16 + bn) * WST + (kl + bk) * 2);
                bl[2*p][0] = q[0]; bl[2*p][1] = q[1];
                bl[2*p+1][0] = q[2]; bl[2*p+1][1] = q[3];
            }
#pragma unroll
            for (int mi = 0; mi < 2; mi++)
#pragma unroll
                for (int ni = 0; ni < 6; ni++) {
                    mma_f16(acc[mi][ni], ah[mi], bh[ni]);
                    mma_f16(acc[mi][ni], ah[mi], bl[ni]);
                    mma_f16(acc[mi][ni], al[mi], bh[ni]);
                }
        }
        if (c < 8) { CP_WAIT0(); __syncthreads(); }
    }

    const int c4 = lane & 3, lr4 = lane >> 2, wnIdx = wid >> 2;
    float pv[2][2] = {{0,0},{0,0}};
#pragma unroll
    for (int mi = 0; mi < 2; mi++)
#pragma unroll
        for (int ni = 0; ni < 6; ni++) {
            int col = wn + 8 * ni + 2 * c4;
            float b0 = prm[col], b1v = prm[col + 1];
            float w0 = prm[192 + col], w1 = prm[192 + col + 1];
            pv[mi][0] += fmaxf(acc[mi][ni][0] + b0, 0.f) * w0 + fmaxf(acc[mi][ni][1] + b1v, 0.f) * w1;
            pv[mi][1] += fmaxf(acc[mi][ni][2] + b0, 0.f) * w0 + fmaxf(acc[mi][ni][3] + b1v, 0.f) * w1;
        }
#pragma unroll
    for (int o = 1; o <= 2; o <<= 1)
#pragma unroll
        for (int mi = 0; mi < 2; mi++)
#pragma unroll
            for (int hf = 0; hf < 2; hf++)
                pv[mi][hf] += __shfl_xor_sync(0xffffffffu, pv[mi][hf], o);
    __syncthreads();
    if (c4 == 0) {
#pragma unroll
        for (int mi = 0; mi < 2; mi++)
#pragma unroll
            for (int hf = 0; hf < 2; hf++) {
                int row = wm + 16 * mi + 8 * hf + lr4;
                part[row * 4 + wnIdx] = pv[mi][hf];
            }
    }
    __syncthreads();
    if (tid < 128 && row0 + tid < Bm) {
        out[row0 + tid] = part[tid*4] + part[tid*4+1] + part[tid*4+2] + part[tid*4+3] + b2[0];
    }
}

// ===== launch =====
extern "C" void kernel_launch(void* const* d_in, const int* in_sizes, int n_in,
                              void* d_out, int out_size)
{
    const int*   z        = (const int*)  d_in[1];
    const float* pos      = (const float*)d_in[2];
    const int*   batch    = (const int*)  d_in[3];
    const float* emb      = (const float*)d_in[5];
    const float* layer_W  = (const float*)d_in[6];
    const float* layer_b  = (const float*)d_in[7];
    const float* layer_g  = (const float*)d_in[8];
    const float* layer_bt = (const float*)d_in[9];
    const float* dist_W   = (const float*)d_in[10];
    const float* dist_b   = (const float*)d_in[11];
    const float* head_W1  = (const float*)d_in[12];
    const float* head_b1  = (const float*)d_in[13];
    const float* head_W2  = (const float*)d_in[14];
    const float* head_b2  = (const float*)d_in[15];
    float* out = (float*)d_out;

    const int B = out_size;
    const int N = in_sizes[1];
    const int L = in_sizes[6] / (H * H);
    const int nrows = 2 * B;

    cudaFuncSetAttribute(layer_mm_kernel, cudaFuncAttributeMaxDynamicSharedMemorySize, L_SMEM);
    cudaFuncSetAttribute(head_mm_kernel,  cudaFuncAttributeMaxDynamicSharedMemorySize, HD_SMEM);

    findfirst_kernel<<<(N + 255) / 256, 256>>>(batch, N, B);
    dist_kernel<<<(B + 255) / 256, 256>>>(pos, B);
    convw_kernel<<<(L * H * H + H * H3 + 255) / 256, 256>>>(layer_W, head_W1, L);

    for (int l = 0; l < L; l++) {
        layer_mm_kernel<<<(nrows + 127) / 128, 512, L_SMEM>>>(
            l, (l == 0) ? 1 : 0, z, emb,
            layer_b + l * H, layer_g + l * H, layer_bt + l * H, nrows, B);
    }
    head_mm_kernel<<<(B + 127) / 128, 512, HD_SMEM>>>(
        head_b1, head_W2, head_b2, dist_W, dist_b, out, B);
}

// round 8
// speedup vs baseline: 9.2587x; 8.9739x over previous
#include <cuda_runtime.h>
#include <math.h>
#include <stdint.h>

#define H 192
#define MAXB 200000
#define MAXZ 8192
#define EPSLN 1e-5f

// ===== device scratch (static, no runtime allocation) =====
__device__ int   g_first[MAXB + 1];
__device__ float g_T0[MAXZ * H];
__device__ float g_T1[MAXZ * H];
__device__ float g_P1[MAXZ * H];
__device__ float g_P2[MAXZ * H];
__device__ float g_u[H];
__device__ float g_v[H];

// ---------------------------------------------------------------------------
// Kernel 1: first atom index of each molecule (batch is sorted)
// ---------------------------------------------------------------------------
__global__ __launch_bounds__(256)
void findfirst_kernel(const int* __restrict__ batch, int N, int B)
{
    int i = blockIdx.x * blockDim.x + threadIdx.x;
    if (i == 0) g_first[B] = N;           // sentinel
    if (i >= N) return;
    if (i == 0 || batch[i] != batch[i - 1])
        g_first[batch[i]] = i;
}

// ---------------------------------------------------------------------------
// Kernel 2: one tower layer over the nz embedding rows.
// h_out = h_in + relu(LN(h_in @ W^T + b) * g + beta)
// Block: 8 rows (one per warp), 256 threads. Lane computes 6 output cols.
// ---------------------------------------------------------------------------
__global__ __launch_bounds__(256)
void tower_layer_kernel(const float* __restrict__ hin, float* __restrict__ hout,
                        const float* __restrict__ Wl, const float* __restrict__ bias,
                        const float* __restrict__ gam, const float* __restrict__ bet,
                        int nz)
{
    __shared__ float hs[8][200];   // 800B row stride, 16B aligned
    const int tid = threadIdx.x;
    const int wid = tid >> 5, lane = tid & 31;
    const int row = blockIdx.x * 8 + wid;

    for (int e = tid; e < 8 * H; e += 256) {
        int r = e / H, c = e - r * H;
        int rr = blockIdx.x * 8 + r;
        hs[r][c] = (rr < nz) ? hin[(size_t)rr * H + c] : 0.f;
    }
    __syncthreads();
    if (row >= nz) return;

    float y[6];
    float s = 0.f, s2 = 0.f;
#pragma unroll
    for (int j = 0; j < 6; j++) {
        int c = lane + 32 * j;
        const float4* wr = (const float4*)(Wl + (size_t)c * H);
        const float4* hr = (const float4*)(hs[wid]);
        float acc = 0.f;
#pragma unroll 4
        for (int k = 0; k < H / 4; k++) {
            float4 w = wr[k], h4 = hr[k];
            acc = fmaf(h4.x, w.x, acc);
            acc = fmaf(h4.y, w.y, acc);
            acc = fmaf(h4.z, w.z, acc);
            acc = fmaf(h4.w, w.w, acc);
        }
        acc += bias[c];
        y[j] = acc; s += acc; s2 += acc * acc;
    }
#pragma unroll
    for (int o = 16; o > 0; o >>= 1) {
        s  += __shfl_xor_sync(0xffffffffu, s,  o);
        s2 += __shfl_xor_sync(0xffffffffu, s2, o);
    }
    float mu = s * (1.f / 192.f);
    float var = s2 * (1.f / 192.f) - mu * mu;
    float rstd = rsqrtf(fmaxf(var, 0.f) + EPSLN);
#pragma unroll
    for (int j = 0; j < 6; j++) {
        int c = lane + 32 * j;
        float v = fmaxf((y[j] - mu) * rstd * gam[c] + bet[c], 0.f);
        hout[(size_t)row * H + c] = hs[wid][c] + v;
    }
}

// ---------------------------------------------------------------------------
// Kernel 3: P1[z] = W1[:, 0:192] @ T[z],  P2[z] = W1[:, 192:384] @ T[z]
// Block b < nz -> P1 row b; b >= nz -> P2 row b-nz. 192 threads, one col each.
// ---------------------------------------------------------------------------
__global__ __launch_bounds__(192)
void ptable_kernel(const float* __restrict__ T, const float* __restrict__ W1, int nz)
{
    __shared__ float ts[H];
    const int b = blockIdx.x;
    const int zr = (b < nz) ? b : b - nz;
    const int off = (b < nz) ? 0 : H;
    float* outp = (b < nz) ? g_P1 : g_P2;
    const int t = threadIdx.x;

    ts[t] = T[(size_t)zr * H + t];
    __syncthreads();

    const float4* wr = (const float4*)(W1 + (size_t)t * 3 * H + off);
    const float4* hr = (const float4*)ts;
    float acc = 0.f;
#pragma unroll 4
    for (int k = 0; k < H / 4; k++) {
        float4 w = wr[k], h4 = hr[k];
        acc = fmaf(h4.x, w.x, acc);
        acc = fmaf(h4.y, w.y, acc);
        acc = fmaf(h4.z, w.z, acc);
        acc = fmaf(h4.w, w.w, acc);
    }
    outp[(size_t)zr * H + t] = acc;
}

// ---------------------------------------------------------------------------
// Kernel 4: u = W1[:, 384:576] @ dW;  v = W1[:, 384:576] @ dB + b1
// One block, 192 threads.
// ---------------------------------------------------------------------------
__global__ __launch_bounds__(192)
void uv_kernel(const float* __restrict__ W1, const float* __restrict__ dW,
               const float* __restrict__ dB, const float* __restrict__ b1)
{
    __shared__ float sw[H], sb[H];
    const int t = threadIdx.x;
    sw[t] = dW[t];
    sb[t] = dB[t];
    __syncthreads();

    const float* wr = W1 + (size_t)t * 3 * H + 2 * H;
    float au = 0.f, av = 0.f;
#pragma unroll 4
    for (int k = 0; k < H; k++) {
        float w = wr[k];
        au = fmaf(w, sw[k], au);
        av = fmaf(w, sb[k], av);
    }
    g_u[t] = au;
    g_v[t] = av + b1[t];
}

// ---------------------------------------------------------------------------
// Kernel 5: per-molecule output. One warp per molecule.
// out[m] = relu(P1[z1] + P2[z2] + dist*u + v) . W2 + b2
// ---------------------------------------------------------------------------
__global__ __launch_bounds__(256)
void final_kernel(const int* __restrict__ z, const float* __restrict__ pos,
                  const float* __restrict__ W2, const float* __restrict__ b2,
                  float* __restrict__ out, int B)
{
    const int gw = (blockIdx.x * blockDim.x + threadIdx.x) >> 5;
    const int lane = threadIdx.x & 31;
    if (gw >= B) return;

    const int f  = g_first[gw];
    const int nf = g_first[gw + 1];
    const bool has2 = (nf - f) > 1;
    const int si = has2 ? f + 1 : f;
    const int z1 = z[f], z2 = z[si];

    float d = 0.f;
    if (has2) {
        float dx = pos[3*f+0] - pos[3*si+0];
        float dy = pos[3*f+1] - pos[3*si+1];
        float dz = pos[3*f+2] - pos[3*si+2];
        d = sqrtf(dx*dx + dy*dy + dz*dz + 1e-12f);
    }

    const float* p1 = g_P1 + (size_t)z1 * H;
    const float* p2 = g_P2 + (size_t)z2 * H;
    float s = 0.f;
#pragma unroll
    for (int j = 0; j < 6; j++) {
        int c = lane + 32 * j;
        float x = p1[c] + p2[c] + d * g_u[c] + g_v[c];
        x = fmaxf(x, 0.f);
        s = fmaf(x, W2[c], s);
    }
#pragma unroll
    for (int o = 16; o > 0; o >>= 1)
        s += __shfl_xor_sync(0xffffffffu, s, o);
    if (lane == 0) out[gw] = s + b2[0];
}

// ---------------------------------------------------------------------------
extern "C" void kernel_launch(void* const* d_in, const int* in_sizes, int n_in,
                              void* d_out, int out_size)
{
    const int*   z        = (const int*)  d_in[1];
    const float* pos      = (const float*)d_in[2];
    const int*   batch    = (const int*)  d_in[3];
    const float* emb      = (const float*)d_in[5];
    const float* layer_W  = (const float*)d_in[6];
    const float* layer_b  = (const float*)d_in[7];
    const float* layer_g  = (const float*)d_in[8];
    const float* layer_bt = (const float*)d_in[9];
    const float* dist_W   = (const float*)d_in[10];
    const float* dist_b   = (const float*)d_in[11];
    const float* head_W1  = (const float*)d_in[12];
    const float* head_b1  = (const float*)d_in[13];
    const float* head_W2  = (const float*)d_in[14];
    const float* head_b2  = (const float*)d_in[15];
    float* out = (float*)d_out;

    const int B  = out_size;                 // molecules
    const int N  = in_sizes[1];              // atoms
    const int nz = in_sizes[5] / H;          // embedding rows (104)
    const int L  = in_sizes[6] / (H * H);    // layers (5)

    // 1. first-atom index per molecule
    findfirst_kernel<<<(N + 255) / 256, 256>>>(batch, N, B);

    // 2. tower over all nz embedding rows, ping-pong T0/T1
    {
        const int tgrid = (nz + 7) / 8;
        const float* cur_in = emb;
        // resolve device-global pointers on host side is not allowed without
        // cudaGetSymbolAddress (allowed: no alloc). Use it once per launch.
        float* t0; float* t1;
        cudaGetSymbolAddress((void**)&t0, g_T0);
        cudaGetSymbolAddress((void**)&t1, g_T1);
        float* bufs[2] = { t0, t1 };
        for (int l = 0; l < L; l++) {
            float* outb = bufs[l & 1];
            tower_layer_kernel<<<tgrid, 256>>>(
                cur_in, outb,
                layer_W + (size_t)l * H * H,
                layer_b + l * H, layer_g + l * H, layer_bt + l * H, nz);
            cur_in = outb;
        }
        // 3. head tables from final tower output
        ptable_kernel<<<2 * nz, 192>>>(cur_in, head_W1, nz);
    }

    // 4. u/v vectors
    uv_kernel<<<1, 192>>>(head_W1, dist_W, dist_b, head_b1);

    // 5. per-molecule output (one warp per molecule)
    final_kernel<<<(B * 32 + 255) / 256, 256>>>(z, pos, head_W2, head_b2, out, B);
}

// round 9
// speedup vs baseline: 25.8572x; 2.7928x over previous
#include <cuda_runtime.h>
#include <math.h>
#include <stdint.h>

#define H 192
#define MAXB 200000
#define MAXZ 8192
#define EPSLN 1e-5f

// ===== device scratch (static, no runtime allocation) =====
__device__ int   g_first[MAXB + 1];
__device__ float g_P1[MAXZ * H];
__device__ float g_P2[MAXZ * H];
__device__ float g_u[H];
__device__ float g_v[H];

// ---------------------------------------------------------------------------
// Kernel 1: first atom index of each molecule (batch is sorted)
// ---------------------------------------------------------------------------
__global__ __launch_bounds__(256)
void findfirst_kernel(const int* __restrict__ batch, int N, int B)
{
    int i = blockIdx.x * blockDim.x + threadIdx.x;
    if (i == 0) g_first[B] = N;           // sentinel
    if (i >= N) return;
    if (i == 0 || batch[i] != batch[i - 1])
        g_first[batch[i]] = i;
}

// ---------------------------------------------------------------------------
// Kernel 2: full tower (all L layers) + P1/P2 table build.
// One block per z-row, 192 threads (thread = one hidden column).
// h lives in smem across layers; LN via warp+smem block reduction.
// ---------------------------------------------------------------------------
__global__ __launch_bounds__(192)
void tower_full_kernel(const float* __restrict__ emb,
                       const float* __restrict__ layer_W,
                       const float* __restrict__ layer_b,
                       const float* __restrict__ layer_g,
                       const float* __restrict__ layer_bt,
                       const float* __restrict__ head_W1,
                       int L)
{
    __shared__ float hs[H];
    __shared__ float red_s[6], red_q[6];

    const int t = threadIdx.x;
    const int zr = blockIdx.x;
    const int wid = t >> 5, lane = t & 31;

    hs[t] = emb[(size_t)zr * H + t];
    __syncthreads();

    for (int l = 0; l < L; l++) {
        const float* Wl = layer_W + (size_t)l * H * H;
        // y_t = dot(Wl[t,:], h) + b[t], 4 independent accumulators
        const float4* wr = (const float4*)(Wl + (size_t)t * H);
        const float4* hr = (const float4*)hs;
        float a0 = 0.f, a1 = 0.f, a2 = 0.f, a3 = 0.f;
#pragma unroll
        for (int k = 0; k < 48; k += 4) {
            float4 w0 = wr[k],     h0 = hr[k];
            float4 w1 = wr[k + 1], h1 = hr[k + 1];
            float4 w2 = wr[k + 2], h2 = hr[k + 2];
            float4 w3 = wr[k + 3], h3 = hr[k + 3];
            a0 = fmaf(h0.x, w0.x, a0); a0 = fmaf(h0.y, w0.y, a0);
            a0 = fmaf(h0.z, w0.z, a0); a0 = fmaf(h0.w, w0.w, a0);
            a1 = fmaf(h1.x, w1.x, a1); a1 = fmaf(h1.y, w1.y, a1);
            a1 = fmaf(h1.z, w1.z, a1); a1 = fmaf(h1.w, w1.w, a1);
            a2 = fmaf(h2.x, w2.x, a2); a2 = fmaf(h2.y, w2.y, a2);
            a2 = fmaf(h2.z, w2.z, a2); a2 = fmaf(h2.w, w2.w, a2);
            a3 = fmaf(h3.x, w3.x, a3); a3 = fmaf(h3.y, w3.y, a3);
            a3 = fmaf(h3.z, w3.z, a3); a3 = fmaf(h3.w, w3.w, a3);
        }
        float y = (a0 + a1) + (a2 + a3) + layer_b[l * H + t];

        // block LN reduction over 192 threads
        float s = y, q = y * y;
#pragma unroll
        for (int o = 16; o > 0; o >>= 1) {
            s += __shfl_xor_sync(0xffffffffu, s, o);
            q += __shfl_xor_sync(0xffffffffu, q, o);
        }
        if (lane == 0) { red_s[wid] = s; red_q[wid] = q; }
        __syncthreads();
        float S = red_s[0] + red_s[1] + red_s[2] + red_s[3] + red_s[4] + red_s[5];
        float Q = red_q[0] + red_q[1] + red_q[2] + red_q[3] + red_q[4] + red_q[5];
        float mu = S * (1.f / 192.f);
        float var = Q * (1.f / 192.f) - mu * mu;
        float rstd = rsqrtf(fmaxf(var, 0.f) + EPSLN);

        float v = fmaxf((y - mu) * rstd * layer_g[l * H + t] + layer_bt[l * H + t], 0.f);
        float hnew = hs[t] + v;
        __syncthreads();          // everyone done reading hs (dot + residual)
        hs[t] = hnew;
        __syncthreads();
    }

    // P1[zr][t] = dot(W1[t, 0:192], h);  P2[zr][t] = dot(W1[t, 192:384], h)
    {
        const float4* w1 = (const float4*)(head_W1 + (size_t)t * 3 * H);
        const float4* w2 = (const float4*)(head_W1 + (size_t)t * 3 * H + H);
        const float4* hr = (const float4*)hs;
        float p1a = 0.f, p1b = 0.f, p2a = 0.f, p2b = 0.f;
#pragma unroll
        for (int k = 0; k < 48; k += 2) {
            float4 ha = hr[k], hb = hr[k + 1];
            float4 wa = w1[k], wb = w1[k + 1];
            p1a = fmaf(ha.x, wa.x, p1a); p1a = fmaf(ha.y, wa.y, p1a);
            p1a = fmaf(ha.z, wa.z, p1a); p1a = fmaf(ha.w, wa.w, p1a);
            p1b = fmaf(hb.x, wb.x, p1b); p1b = fmaf(hb.y, wb.y, p1b);
            p1b = fmaf(hb.z, wb.z, p1b); p1b = fmaf(hb.w, wb.w, p1b);
            float4 va = w2[k], vb = w2[k + 1];
            p2a = fmaf(ha.x, va.x, p2a); p2a = fmaf(ha.y, va.y, p2a);
            p2a = fmaf(ha.z, va.z, p2a); p2a = fmaf(ha.w, va.w, p2a);
            p2b = fmaf(hb.x, vb.x, p2b); p2b = fmaf(hb.y, vb.y, p2b);
            p2b = fmaf(hb.z, vb.z, p2b); p2b = fmaf(hb.w, vb.w, p2b);
        }
        g_P1[(size_t)zr * H + t] = p1a + p1b;
        g_P2[(size_t)zr * H + t] = p2a + p2b;
    }
}

// ---------------------------------------------------------------------------
// Kernel 3: u = W1[:, 384:576] @ dW;  v = W1[:, 384:576] @ dB + b1
// ---------------------------------------------------------------------------
__global__ __launch_bounds__(192)
void uv_kernel(const float* __restrict__ W1, const float* __restrict__ dW,
               const float* __restrict__ dB, const float* __restrict__ b1)
{
    __shared__ float sw[H], sb[H];
    const int t = threadIdx.x;
    sw[t] = dW[t];
    sb[t] = dB[t];
    __syncthreads();

    const float* wr = W1 + (size_t)t * 3 * H + 2 * H;
    float au = 0.f, av = 0.f;
#pragma unroll 4
    for (int k = 0; k < H; k++) {
        float w = wr[k];
        au = fmaf(w, sw[k], au);
        av = fmaf(w, sb[k], av);
    }
    g_u[t] = au;
    g_v[t] = av + b1[t];
}

// ---------------------------------------------------------------------------
// Kernel 4: per-molecule output. One warp per molecule.
// out[m] = relu(P1[z1] + P2[z2] + dist*u + v) . W2 + b2
// ---------------------------------------------------------------------------
__global__ __launch_bounds__(256)
void final_kernel(const int* __restrict__ z, const float* __restrict__ pos,
                  const float* __restrict__ W2, const float* __restrict__ b2,
                  float* __restrict__ out, int B)
{
    const int gw = (blockIdx.x * blockDim.x + threadIdx.x) >> 5;
    const int lane = threadIdx.x & 31;
    if (gw >= B) return;

    const int f  = g_first[gw];
    const int nf = g_first[gw + 1];
    const bool has2 = (nf - f) > 1;
    const int si = has2 ? f + 1 : f;
    const int z1 = z[f], z2 = z[si];

    float d = 0.f;
    if (has2) {
        float dx = pos[3*f+0] - pos[3*si+0];
        float dy = pos[3*f+1] - pos[3*si+1];
        float dz = pos[3*f+2] - pos[3*si+2];
        d = sqrtf(dx*dx + dy*dy + dz*dz + 1e-12f);
    }

    const float* p1 = g_P1 + (size_t)z1 * H;
    const float* p2 = g_P2 + (size_t)z2 * H;
    float s = 0.f;
#pragma unroll
    for (int j = 0; j < 6; j++) {
        int c = lane + 32 * j;
        float x = p1[c] + p2[c] + d * g_u[c] + g_v[c];
        x = fmaxf(x, 0.f);
        s = fmaf(x, W2[c], s);
    }
#pragma unroll
    for (int o = 16; o > 0; o >>= 1)
        s += __shfl_xor_sync(0xffffffffu, s, o);
    if (lane == 0) out[gw] = s + b2[0];
}

// ---------------------------------------------------------------------------
extern "C" void kernel_launch(void* const* d_in, const int* in_sizes, int n_in,
                              void* d_out, int out_size)
{
    const int*   z        = (const int*)  d_in[1];
    const float* pos      = (const float*)d_in[2];
    const int*   batch    = (const int*)  d_in[3];
    const float* emb      = (const float*)d_in[5];
    const float* layer_W  = (const float*)d_in[6];
    const float* layer_b  = (const float*)d_in[7];
    const float* layer_g  = (const float*)d_in[8];
    const float* layer_bt = (const float*)d_in[9];
    const float* dist_W   = (const float*)d_in[10];
    const float* dist_b   = (const float*)d_in[11];
    const float* head_W1  = (const float*)d_in[12];
    const float* head_b1  = (const float*)d_in[13];
    const float* head_W2  = (const float*)d_in[14];
    const float* head_b2  = (const float*)d_in[15];
    float* out = (float*)d_out;

    const int B  = out_size;                 // molecules
    const int N  = in_sizes[1];              // atoms
    const int nz = in_sizes[5] / H;          // embedding rows (104)
    const int L  = in_sizes[6] / (H * H);    // layers (5)

    findfirst_kernel<<<(N + 255) / 256, 256>>>(batch, N, B);
    tower_full_kernel<<<nz, 192>>>(emb, layer_W, layer_b, layer_g, layer_bt,
                                   head_W1, L);
    uv_kernel<<<1, 192>>>(head_W1, dist_W, dist_b, head_b1);
    final_kernel<<<(B * 32 + 255) / 256, 256>>>(z, pos, head_W2, head_b2, out, B);
}

// round 10
// speedup vs baseline: 26.1950x; 1.0131x over previous
#include <cuda_runtime.h>
#include <math.h>
#include <stdint.h>

#define H 192
#define MAXB 200000
#define MAXZ 8192
#define EPSLN 1e-5f

// ===== device scratch (static, no runtime allocation) =====
__device__ int   g_first[MAXB + 1];
__device__ float g_P1[MAXZ * H];
__device__ float g_P2[MAXZ * H];
__device__ float g_u[H];
__device__ float g_v[H];

// ---------------------------------------------------------------------------
// Kernel A: heterogeneous grid.
//   block <  nz        : full tower (L layers) for z-row `block` + P1/P2 rows
//   block == nz        : u/v vectors
//   block >  nz        : findfirst scan chunk
// 256 threads per block (tower/uv use first 192).
// ---------------------------------------------------------------------------
__global__ __launch_bounds__(256)
void prep_kernel(const int* __restrict__ batch, int N, int B,
                 const float* __restrict__ emb,
                 const float* __restrict__ layer_W,
                 const float* __restrict__ layer_b,
                 const float* __restrict__ layer_g,
                 const float* __restrict__ layer_bt,
                 const float* __restrict__ head_W1,
                 const float* __restrict__ dW, const float* __restrict__ dB,
                 const float* __restrict__ b1,
                 int L, int nz)
{
    const int tid = threadIdx.x;
    const int bx  = blockIdx.x;

    if (bx > nz) {
        // ---- findfirst ----
        int i = (bx - nz - 1) * 256 + tid;
        if (i == 0) g_first[B] = N;          // sentinel
        if (i < N && (i == 0 || batch[i] != batch[i - 1]))
            g_first[batch[i]] = i;
        return;
    }

    if (bx == nz) {
        // ---- u/v ----
        __shared__ float sw[H], sb2[H];
        if (tid < H) { sw[tid] = dW[tid]; sb2[tid] = dB[tid]; }
        __syncthreads();
        if (tid < H) {
            const float* wr = head_W1 + (size_t)tid * 3 * H + 2 * H;
            float au = 0.f, av = 0.f;
#pragma unroll 4
            for (int k = 0; k < H; k++) {
                float w = wr[k];
                au = fmaf(w, sw[k], au);
                av = fmaf(w, sb2[k], av);
            }
            g_u[tid] = au;
            g_v[tid] = av + b1[tid];
        }
        return;
    }

    // ---- tower for z-row bx ----
    __shared__ float hs[H];
    __shared__ float red_s[6], red_q[6];
    const int t = tid;                      // 0..255; active math on t<192
    const int wid = t >> 5, lane = t & 31;

    if (t < H) hs[t] = emb[(size_t)bx * H + t];
    __syncthreads();

    for (int l = 0; l < L; l++) {
        float y = 0.f;
        if (t < H) {
            const float4* wr = (const float4*)(layer_W + (size_t)l * H * H + (size_t)t * H);
            const float4* hr = (const float4*)hs;
            float a0 = 0.f, a1 = 0.f, a2 = 0.f, a3 = 0.f;
#pragma unroll
            for (int k = 0; k < 48; k += 4) {
                float4 w0 = wr[k],     h0 = hr[k];
                float4 w1 = wr[k + 1], h1 = hr[k + 1];
                float4 w2 = wr[k + 2], h2 = hr[k + 2];
                float4 w3 = wr[k + 3], h3 = hr[k + 3];
                a0 = fmaf(h0.x, w0.x, a0); a0 = fmaf(h0.y, w0.y, a0);
                a0 = fmaf(h0.z, w0.z, a0); a0 = fmaf(h0.w, w0.w, a0);
                a1 = fmaf(h1.x, w1.x, a1); a1 = fmaf(h1.y, w1.y, a1);
                a1 = fmaf(h1.z, w1.z, a1); a1 = fmaf(h1.w, w1.w, a1);
                a2 = fmaf(h2.x, w2.x, a2); a2 = fmaf(h2.y, w2.y, a2);
                a2 = fmaf(h2.z, w2.z, a2); a2 = fmaf(h2.w, w2.w, a2);
                a3 = fmaf(h3.x, w3.x, a3); a3 = fmaf(h3.y, w3.y, a3);
                a3 = fmaf(h3.z, w3.z, a3); a3 = fmaf(h3.w, w3.w, a3);
            }
            y = (a0 + a1) + (a2 + a3) + layer_b[l * H + t];
        }
        // LN block reduction (warps 0-5 hold 192 values)
        float s = y, q = y * y;
#pragma unroll
        for (int o = 16; o > 0; o >>= 1) {
            s += __shfl_xor_sync(0xffffffffu, s, o);
            q += __shfl_xor_sync(0xffffffffu, q, o);
        }
        if (lane == 0 && wid < 6) { red_s[wid] = s; red_q[wid] = q; }
        __syncthreads();
        float S = red_s[0] + red_s[1] + red_s[2] + red_s[3] + red_s[4] + red_s[5];
        float Q = red_q[0] + red_q[1] + red_q[2] + red_q[3] + red_q[4] + red_q[5];
        float mu = S * (1.f / 192.f);
        float var = Q * (1.f / 192.f) - mu * mu;
        float rstd = rsqrtf(fmaxf(var, 0.f) + EPSLN);

        float hnew = 0.f;
        if (t < H) {
            float v = fmaxf((y - mu) * rstd * layer_g[l * H + t] + layer_bt[l * H + t], 0.f);
            hnew = hs[t] + v;
        }
        __syncthreads();                    // all reads of hs done
        if (t < H) hs[t] = hnew;
        __syncthreads();
    }

    // P1/P2 rows
    if (t < H) {
        const float4* w1 = (const float4*)(head_W1 + (size_t)t * 3 * H);
        const float4* w2 = (const float4*)(head_W1 + (size_t)t * 3 * H + H);
        const float4* hr = (const float4*)hs;
        float p1a = 0.f, p1b = 0.f, p2a = 0.f, p2b = 0.f;
#pragma unroll
        for (int k = 0; k < 48; k += 2) {
            float4 ha = hr[k], hb = hr[k + 1];
            float4 wa = w1[k], wb = w1[k + 1];
            p1a = fmaf(ha.x, wa.x, p1a); p1a = fmaf(ha.y, wa.y, p1a);
            p1a = fmaf(ha.z, wa.z, p1a); p1a = fmaf(ha.w, wa.w, p1a);
            p1b = fmaf(hb.x, wb.x, p1b); p1b = fmaf(hb.y, wb.y, p1b);
            p1b = fmaf(hb.z, wb.z, p1b); p1b = fmaf(hb.w, wb.w, p1b);
            float4 va = w2[k], vb = w2[k + 1];
            p2a = fmaf(ha.x, va.x, p2a); p2a = fmaf(ha.y, va.y, p2a);
            p2a = fmaf(ha.z, va.z, p2a); p2a = fmaf(ha.w, va.w, p2a);
            p2b = fmaf(hb.x, vb.x, p2b); p2b = fmaf(hb.y, vb.y, p2b);
            p2b = fmaf(hb.z, vb.z, p2b); p2b = fmaf(hb.w, vb.w, p2b);
        }
        g_P1[(size_t)bx * H + t] = p1a + p1b;
        g_P2[(size_t)bx * H + t] = p2a + p2b;
    }
}

// ---------------------------------------------------------------------------
// Kernel B: final. Persistent warps, P1/P2 tables in shared memory.
// Warp handles molecules m = gwarp, gwarp + totalWarps, ...
// ---------------------------------------------------------------------------
__global__ __launch_bounds__(512, 1)
void final_kernel(const int* __restrict__ z, const float* __restrict__ pos,
                  const float* __restrict__ W2, const float* __restrict__ b2,
                  float* __restrict__ out, int B, int nz)
{
    extern __shared__ float tbl[];         // [nz*H] P1 | [nz*H] P2
    const int tid = threadIdx.x;
    const int wid = tid >> 5, lane = tid & 31;

    // load tables (float4)
    {
        const float4* s1 = (const float4*)g_P1;
        const float4* s2 = (const float4*)g_P2;
        float4* d1 = (float4*)tbl;
        float4* d2 = (float4*)(tbl + (size_t)nz * H);
        const int n4 = nz * H / 4;
        for (int i = tid; i < n4; i += 512) { d1[i] = s1[i]; d2[i] = s2[i]; }
    }
    // per-lane constants
    float uu[6], vv[6], ww[6];
#pragma unroll
    for (int j = 0; j < 6; j++) {
        int c = lane + 32 * j;
        uu[j] = g_u[c]; vv[j] = g_v[c]; ww[j] = W2[c];
    }
    const float b2v = b2[0];
    __syncthreads();

    const float* P1s = tbl;
    const float* P2s = tbl + (size_t)nz * H;
    const int totalWarps = gridDim.x * 16;
    for (int m = blockIdx.x * 16 + wid; m < B; m += totalWarps) {
        const int f  = g_first[m];
        const int nf = g_first[m + 1];
        const bool has2 = (nf - f) > 1;
        const int si = has2 ? f + 1 : f;
        const int z1 = z[f], z2 = z[si];

        // 6 coords in one LDG via lane split
        float pv = 0.f;
        if (lane < 6) {
            int a = (lane < 3) ? f : si;
            pv = pos[3 * a + (lane < 3 ? lane : lane - 3)];
        }
        float ax = __shfl_sync(0xffffffffu, pv, 0) - __shfl_sync(0xffffffffu, pv, 3);
        float ay = __shfl_sync(0xffffffffu, pv, 1) - __shfl_sync(0xffffffffu, pv, 4);
        float az = __shfl_sync(0xffffffffu, pv, 2) - __shfl_sync(0xffffffffu, pv, 5);
        float d = has2 ? sqrtf(ax * ax + ay * ay + az * az + 1e-12f) : 0.f;

        const float* p1 = P1s + (size_t)z1 * H;
        const float* p2 = P2s + (size_t)z2 * H;
        float s = 0.f;
#pragma unroll
        for (int j = 0; j < 6; j++) {
            int c = lane + 32 * j;
            float x = p1[c] + p2[c] + fmaf(d, uu[j], vv[j]);
            s = fmaf(fmaxf(x, 0.f), ww[j], s);
        }
#pragma unroll
        for (int o = 16; o > 0; o >>= 1)
            s += __shfl_xor_sync(0xffffffffu, s, o);
        if (lane == 0) out[m] = s + b2v;
    }
}

// ---------------------------------------------------------------------------
extern "C" void kernel_launch(void* const* d_in, const int* in_sizes, int n_in,
                              void* d_out, int out_size)
{
    const int*   z        = (const int*)  d_in[1];
    const float* pos      = (const float*)d_in[2];
    const int*   batch    = (const int*)  d_in[3];
    const float* emb      = (const float*)d_in[5];
    const float* layer_W  = (const float*)d_in[6];
    const float* layer_b  = (const float*)d_in[7];
    const float* layer_g  = (const float*)d_in[8];
    const float* layer_bt = (const float*)d_in[9];
    const float* dist_W   = (const float*)d_in[10];
    const float* dist_b   = (const float*)d_in[11];
    const float* head_W1  = (const float*)d_in[12];
    const float* head_b1  = (const float*)d_in[13];
    const float* head_W2  = (const float*)d_in[14];
    const float* head_b2  = (const float*)d_in[15];
    float* out = (float*)d_out;

    const int B  = out_size;                 // molecules
    const int N  = in_sizes[1];              // atoms
    const int nz = in_sizes[5] / H;          // embedding rows (104)
    const int L  = in_sizes[6] / (H * H);    // layers (5)

    // Kernel A: tower (nz blocks) + uv (1) + findfirst (ceil(N/256))
    const int gridA = nz + 1 + (N + 255) / 256;
    prep_kernel<<<gridA, 256>>>(batch, N, B, emb, layer_W, layer_b, layer_g,
                                layer_bt, head_W1, dist_W, dist_b, head_b1,
                                L, nz);

    // Kernel B: final, tables in smem
    const int smemB = 2 * nz * H * (int)sizeof(float);   // 159,744 B for nz=104
    cudaFuncSetAttribute(final_kernel, cudaFuncAttributeMaxDynamicSharedMemorySize, smemB);
    final_kernel<<<148, 512, smemB>>>(z, pos, head_W2, head_b2, out, B, nz);
}

// round 11
// speedup vs baseline: 33.4194x; 1.2758x over previous
#include <cuda_runtime.h>
#include <math.h>
#include <stdint.h>

#define H 192
#define MAXB 200000
#define MAXZ 8192
#define EPSLN 1e-5f

// ===== device scratch (static, no runtime allocation) =====
__device__ int   g_first[MAXB + 1];
__device__ float g_P1[MAXZ * H];
__device__ float g_P2[MAXZ * H];
__device__ float g_u[H];
__device__ float g_v[H];

// ---------------------------------------------------------------------------
// Kernel A: heterogeneous grid.
//   block <  nz : full tower (L layers) for z-row `block` + P1/P2 rows
//   block == nz : u/v vectors
//   block >  nz : findfirst scan chunk
// ---------------------------------------------------------------------------
__global__ __launch_bounds__(256)
void prep_kernel(const int* __restrict__ batch, int N, int B,
                 const float* __restrict__ emb,
                 const float* __restrict__ layer_W,
                 const float* __restrict__ layer_b,
                 const float* __restrict__ layer_g,
                 const float* __restrict__ layer_bt,
                 const float* __restrict__ head_W1,
                 const float* __restrict__ dW, const float* __restrict__ dB,
                 const float* __restrict__ b1,
                 int L, int nz)
{
    const int tid = threadIdx.x;
    const int bx  = blockIdx.x;

    if (bx > nz) {
        // ---- findfirst ----
        int i = (bx - nz - 1) * 256 + tid;
        if (i == 0) g_first[B] = N;          // sentinel
        if (i < N && (i == 0 || batch[i] != batch[i - 1]))
            g_first[batch[i]] = i;
        return;
    }

    if (bx == nz) {
        // ---- u/v ----
        __shared__ float sw[H], sb2[H];
        if (tid < H) { sw[tid] = dW[tid]; sb2[tid] = dB[tid]; }
        __syncthreads();
        if (tid < H) {
            const float* wr = head_W1 + (size_t)tid * 3 * H + 2 * H;
            float au = 0.f, av = 0.f;
#pragma unroll 4
            for (int k = 0; k < H; k++) {
                float w = wr[k];
                au = fmaf(w, sw[k], au);
                av = fmaf(w, sb2[k], av);
            }
            g_u[tid] = au;
            g_v[tid] = av + b1[tid];
        }
        return;
    }

    // ---- tower for z-row bx ----
    __shared__ float hs[H];
    __shared__ float red_s[6], red_q[6];
    const int t = tid;
    const int wid = t >> 5, lane = t & 31;

    if (t < H) hs[t] = emb[(size_t)bx * H + t];
    __syncthreads();

    for (int l = 0; l < L; l++) {
        float y = 0.f;
        if (t < H) {
            const float4* wr = (const float4*)(layer_W + (size_t)l * H * H + (size_t)t * H);
            const float4* hr = (const float4*)hs;
            float a0 = 0.f, a1 = 0.f, a2 = 0.f, a3 = 0.f;
#pragma unroll
            for (int k = 0; k < 48; k += 4) {
                float4 w0 = wr[k],     h0 = hr[k];
                float4 w1 = wr[k + 1], h1 = hr[k + 1];
                float4 w2 = wr[k + 2], h2 = hr[k + 2];
                float4 w3 = wr[k + 3], h3 = hr[k + 3];
                a0 = fmaf(h0.x, w0.x, a0); a0 = fmaf(h0.y, w0.y, a0);
                a0 = fmaf(h0.z, w0.z, a0); a0 = fmaf(h0.w, w0.w, a0);
                a1 = fmaf(h1.x, w1.x, a1); a1 = fmaf(h1.y, w1.y, a1);
                a1 = fmaf(h1.z, w1.z, a1); a1 = fmaf(h1.w, w1.w, a1);
                a2 = fmaf(h2.x, w2.x, a2); a2 = fmaf(h2.y, w2.y, a2);
                a2 = fmaf(h2.z, w2.z, a2); a2 = fmaf(h2.w, w2.w, a2);
                a3 = fmaf(h3.x, w3.x, a3); a3 = fmaf(h3.y, w3.y, a3);
                a3 = fmaf(h3.z, w3.z, a3); a3 = fmaf(h3.w, w3.w, a3);
            }
            y = (a0 + a1) + (a2 + a3) + layer_b[l * H + t];
        }
        float s = y, q = y * y;
#pragma unroll
        for (int o = 16; o > 0; o >>= 1) {
            s += __shfl_xor_sync(0xffffffffu, s, o);
            q += __shfl_xor_sync(0xffffffffu, q, o);
        }
        if (lane == 0 && wid < 6) { red_s[wid] = s; red_q[wid] = q; }
        __syncthreads();
        float S = red_s[0] + red_s[1] + red_s[2] + red_s[3] + red_s[4] + red_s[5];
        float Q = red_q[0] + red_q[1] + red_q[2] + red_q[3] + red_q[4] + red_q[5];
        float mu = S * (1.f / 192.f);
        float var = Q * (1.f / 192.f) - mu * mu;
        float rstd = rsqrtf(fmaxf(var, 0.f) + EPSLN);

        float hnew = 0.f;
        if (t < H) {
            float v = fmaxf((y - mu) * rstd * layer_g[l * H + t] + layer_bt[l * H + t], 0.f);
            hnew = hs[t] + v;
        }
        __syncthreads();
        if (t < H) hs[t] = hnew;
        __syncthreads();
    }

    if (t < H) {
        const float4* w1 = (const float4*)(head_W1 + (size_t)t * 3 * H);
        const float4* w2 = (const float4*)(head_W1 + (size_t)t * 3 * H + H);
        const float4* hr = (const float4*)hs;
        float p1a = 0.f, p1b = 0.f, p2a = 0.f, p2b = 0.f;
#pragma unroll
        for (int k = 0; k < 48; k += 2) {
            float4 ha = hr[k], hb = hr[k + 1];
            float4 wa = w1[k], wb = w1[k + 1];
            p1a = fmaf(ha.x, wa.x, p1a); p1a = fmaf(ha.y, wa.y, p1a);
            p1a = fmaf(ha.z, wa.z, p1a); p1a = fmaf(ha.w, wa.w, p1a);
            p1b = fmaf(hb.x, wb.x, p1b); p1b = fmaf(hb.y, wb.y, p1b);
            p1b = fmaf(hb.z, wb.z, p1b); p1b = fmaf(hb.w, wb.w, p1b);
            float4 va = w2[k], vb = w2[k + 1];
            p2a = fmaf(ha.x, va.x, p2a); p2a = fmaf(ha.y, va.y, p2a);
            p2a = fmaf(ha.z, va.z, p2a); p2a = fmaf(ha.w, va.w, p2a);
            p2b = fmaf(hb.x, vb.x, p2b); p2b = fmaf(hb.y, vb.y, p2b);
            p2b = fmaf(hb.z, vb.z, p2b); p2b = fmaf(hb.w, vb.w, p2b);
        }
        g_P1[(size_t)bx * H + t] = p1a + p1b;
        g_P2[(size_t)bx * H + t] = p2a + p2b;
    }
}

// ---------------------------------------------------------------------------
// Kernel B: final. Persistent warps, NO smem table (tables via L1/L2),
// u/v/W2/b2 hoisted to registers, float2-vectorized table reads.
// Lane owns columns {2*lane + 64j, 2*lane + 64j + 1}, j = 0..2.
// ---------------------------------------------------------------------------
__global__ __launch_bounds__(256)
void final_kernel(const int* __restrict__ z, const float* __restrict__ pos,
                  const float* __restrict__ W2, const float* __restrict__ b2,
                  float* __restrict__ out, int B)
{
    const int tid = threadIdx.x;
    const int wid = tid >> 5, lane = tid & 31;

    // hoisted per-lane constants (float2 layout matching table reads)
    float2 uu[3], vv[3], ww[3];
#pragma unroll
    for (int j = 0; j < 3; j++) {
        int c = 2 * lane + 64 * j;
        uu[j] = *(const float2*)(g_u + c);
        vv[j] = *(const float2*)(g_v + c);
        ww[j] = *(const float2*)(W2 + c);
    }
    const float b2v = b2[0];

    const int warpsTotal = gridDim.x * 8;
    for (int m = blockIdx.x * 8 + wid; m < B; m += warpsTotal) {
        const int f  = __ldg(g_first + m);
        const int nf = __ldg(g_first + m + 1);
        const bool has2 = (nf - f) > 1;
        const int si = has2 ? f + 1 : f;
        const int z1 = __ldg(z + f), z2 = __ldg(z + si);

        // 6 coords via lane split (one LDG)
        float pv = 0.f;
        if (lane < 6) {
            int a = (lane < 3) ? f : si;
            pv = pos[3 * a + (lane < 3 ? lane : lane - 3)];
        }
        float ax = __shfl_sync(0xffffffffu, pv, 0) - __shfl_sync(0xffffffffu, pv, 3);
        float ay = __shfl_sync(0xffffffffu, pv, 1) - __shfl_sync(0xffffffffu, pv, 4);
        float az = __shfl_sync(0xffffffffu, pv, 2) - __shfl_sync(0xffffffffu, pv, 5);
        float d = has2 ? sqrtf(ax * ax + ay * ay + az * az + 1e-12f) : 0.f;

        const float2* p1 = (const float2*)(g_P1 + (size_t)z1 * H) + lane;
        const float2* p2 = (const float2*)(g_P2 + (size_t)z2 * H) + lane;
        // issue all 6 table loads up front (MLP)
        float2 a0 = __ldg(p1 +  0), b0 = __ldg(p2 +  0);
        float2 a1 = __ldg(p1 + 32), b1 = __ldg(p2 + 32);
        float2 a2 = __ldg(p1 + 64), b2l = __ldg(p2 + 64);

        float s = 0.f;
        {
            float x0 = a0.x + b0.x + fmaf(d, uu[0].x, vv[0].x);
            float x1 = a0.y + b0.y + fmaf(d, uu[0].y, vv[0].y);
            s = fmaf(fmaxf(x0, 0.f), ww[0].x, s);
            s = fmaf(fmaxf(x1, 0.f), ww[0].y, s);
            x0 = a1.x + b1.x + fmaf(d, uu[1].x, vv[1].x);
            x1 = a1.y + b1.y + fmaf(d, uu[1].y, vv[1].y);
            s = fmaf(fmaxf(x0, 0.f), ww[1].x, s);
            s = fmaf(fmaxf(x1, 0.f), ww[1].y, s);
            x0 = a2.x + b2l.x + fmaf(d, uu[2].x, vv[2].x);
            x1 = a2.y + b2l.y + fmaf(d, uu[2].y, vv[2].y);
            s = fmaf(fmaxf(x0, 0.f), ww[2].x, s);
            s = fmaf(fmaxf(x1, 0.f), ww[2].y, s);
        }
#pragma unroll
        for (int o = 16; o > 0; o >>= 1)
            s += __shfl_xor_sync(0xffffffffu, s, o);
        if (lane == 0) out[m] = s + b2v;
    }
}

// ---------------------------------------------------------------------------
extern "C" void kernel_launch(void* const* d_in, const int* in_sizes, int n_in,
                              void* d_out, int out_size)
{
    const int*   z        = (const int*)  d_in[1];
    const float* pos      = (const float*)d_in[2];
    const int*   batch    = (const int*)  d_in[3];
    const float* emb      = (const float*)d_in[5];
    const float* layer_W  = (const float*)d_in[6];
    const float* layer_b  = (const float*)d_in[7];
    const float* layer_g  = (const float*)d_in[8];
    const float* layer_bt = (const float*)d_in[9];
    const float* dist_W   = (const float*)d_in[10];
    const float* dist_b   = (const float*)d_in[11];
    const float* head_W1  = (const float*)d_in[12];
    const float* head_b1  = (const float*)d_in[13];
    const float* head_W2  = (const float*)d_in[14];
    const float* head_b2  = (const float*)d_in[15];
    float* out = (float*)d_out;

    const int B  = out_size;                 // molecules
    const int N  = in_sizes[1];              // atoms
    const int nz = in_sizes[5] / H;          // embedding rows (104)
    const int L  = in_sizes[6] / (H * H);    // layers (5)

    const int gridA = nz + 1 + (N + 255) / 256;
    prep_kernel<<<gridA, 256>>>(batch, N, B, emb, layer_W, layer_b, layer_g,
                                layer_bt, head_W1, dist_W, dist_b, head_b1,
                                L, nz);

    final_kernel<<<148 * 4, 256>>>(z, pos, head_W2, head_b2, out, B);
}

// round 12
// speedup vs baseline: 41.7329x; 1.2488x over previous
#include <cuda_runtime.h>
#include <math.h>
#include <stdint.h>

#define H 192
#define MAXB 200000
#define MAXZ 8192
#define EPSLN 1e-5f

// ===== device scratch (static, no runtime allocation) =====
__device__ int   g_first[MAXB + 1];
__device__ float g_P1[MAXZ * H];
__device__ float g_P2[MAXZ * H];
__device__ float g_u[H];
__device__ float g_v[H];

// ---------------------------------------------------------------------------
// Kernel A: heterogeneous grid.
//   block <  nz : full tower (L layers) for z-row `block` + P1/P2 rows
//   block == nz : u/v vectors
//   block >  nz : findfirst scan chunk
// ---------------------------------------------------------------------------
__global__ __launch_bounds__(256)
void prep_kernel(const int* __restrict__ batch, int N, int B,
                 const float* __restrict__ emb,
                 const float* __restrict__ layer_W,
                 const float* __restrict__ layer_b,
                 const float* __restrict__ layer_g,
                 const float* __restrict__ layer_bt,
                 const float* __restrict__ head_W1,
                 const float* __restrict__ dW, const float* __restrict__ dB,
                 const float* __restrict__ b1,
                 int L, int nz)
{
    const int tid = threadIdx.x;
    const int bx  = blockIdx.x;

    if (bx > nz) {
        // ---- findfirst ----
        int i = (bx - nz - 1) * 256 + tid;
        if (i == 0) g_first[B] = N;          // sentinel
        if (i < N && (i == 0 || batch[i] != batch[i - 1]))
            g_first[batch[i]] = i;
        return;
    }

    if (bx == nz) {
        // ---- u/v ----
        __shared__ float sw[H], sb2[H];
        if (tid < H) { sw[tid] = dW[tid]; sb2[tid] = dB[tid]; }
        __syncthreads();
        if (tid < H) {
            const float* wr = head_W1 + (size_t)tid * 3 * H + 2 * H;
            float au = 0.f, av = 0.f;
#pragma unroll 4
            for (int k = 0; k < H; k++) {
                float w = wr[k];
                au = fmaf(w, sw[k], au);
                av = fmaf(w, sb2[k], av);
            }
            g_u[tid] = au;
            g_v[tid] = av + b1[tid];
        }
        return;
    }

    // ---- tower for z-row bx ----
    __shared__ float hs[H];
    __shared__ float red_s[6], red_q[6];
    const int t = tid;
    const int wid = t >> 5, lane = t & 31;

    if (t < H) hs[t] = emb[(size_t)bx * H + t];
    __syncthreads();

    for (int l = 0; l < L; l++) {
        float y = 0.f;
        if (t < H) {
            const float4* wr = (const float4*)(layer_W + (size_t)l * H * H + (size_t)t * H);
            const float4* hr = (const float4*)hs;
            float a0 = 0.f, a1 = 0.f, a2 = 0.f, a3 = 0.f;
#pragma unroll
            for (int k = 0; k < 48; k += 4) {
                float4 w0 = wr[k],     h0 = hr[k];
                float4 w1 = wr[k + 1], h1 = hr[k + 1];
                float4 w2 = wr[k + 2], h2 = hr[k + 2];
                float4 w3 = wr[k + 3], h3 = hr[k + 3];
                a0 = fmaf(h0.x, w0.x, a0); a0 = fmaf(h0.y, w0.y, a0);
                a0 = fmaf(h0.z, w0.z, a0); a0 = fmaf(h0.w, w0.w, a0);
                a1 = fmaf(h1.x, w1.x, a1); a1 = fmaf(h1.y, w1.y, a1);
                a1 = fmaf(h1.z, w1.z, a1); a1 = fmaf(h1.w, w1.w, a1);
                a2 = fmaf(h2.x, w2.x, a2); a2 = fmaf(h2.y, w2.y, a2);
                a2 = fmaf(h2.z, w2.z, a2); a2 = fmaf(h2.w, w2.w, a2);
                a3 = fmaf(h3.x, w3.x, a3); a3 = fmaf(h3.y, w3.y, a3);
                a3 = fmaf(h3.z, w3.z, a3); a3 = fmaf(h3.w, w3.w, a3);
            }
            y = (a0 + a1) + (a2 + a3) + layer_b[l * H + t];
        }
        float s = y, q = y * y;
#pragma unroll
        for (int o = 16; o > 0; o >>= 1) {
            s += __shfl_xor_sync(0xffffffffu, s, o);
            q += __shfl_xor_sync(0xffffffffu, q, o);
        }
        if (lane == 0 && wid < 6) { red_s[wid] = s; red_q[wid] = q; }
        __syncthreads();
        float S = red_s[0] + red_s[1] + red_s[2] + red_s[3] + red_s[4] + red_s[5];
        float Q = red_q[0] + red_q[1] + red_q[2] + red_q[3] + red_q[4] + red_q[5];
        float mu = S * (1.f / 192.f);
        float var = Q * (1.f / 192.f) - mu * mu;
        float rstd = rsqrtf(fmaxf(var, 0.f) + EPSLN);

        float hnew = 0.f;
        if (t < H) {
            float v = fmaxf((y - mu) * rstd * layer_g[l * H + t] + layer_bt[l * H + t], 0.f);
            hnew = hs[t] + v;
        }
        __syncthreads();
        if (t < H) hs[t] = hnew;
        __syncthreads();
    }

    if (t < H) {
        const float4* w1 = (const float4*)(head_W1 + (size_t)t * 3 * H);
        const float4* w2 = (const float4*)(head_W1 + (size_t)t * 3 * H + H);
        const float4* hr = (const float4*)hs;
        float p1a = 0.f, p1b = 0.f, p2a = 0.f, p2b = 0.f;
#pragma unroll
        for (int k = 0; k < 48; k += 2) {
            float4 ha = hr[k], hb = hr[k + 1];
            float4 wa = w1[k], wb = w1[k + 1];
            p1a = fmaf(ha.x, wa.x, p1a); p1a = fmaf(ha.y, wa.y, p1a);
            p1a = fmaf(ha.z, wa.z, p1a); p1a = fmaf(ha.w, wa.w, p1a);
            p1b = fmaf(hb.x, wb.x, p1b); p1b = fmaf(hb.y, wb.y, p1b);
            p1b = fmaf(hb.z, wb.z, p1b); p1b = fmaf(hb.w, wb.w, p1b);
            float4 va = w2[k], vb = w2[k + 1];
            p2a = fmaf(ha.x, va.x, p2a); p2a = fmaf(ha.y, va.y, p2a);
            p2a = fmaf(ha.z, va.z, p2a); p2a = fmaf(ha.w, va.w, p2a);
            p2b = fmaf(hb.x, vb.x, p2b); p2b = fmaf(hb.y, vb.y, p2b);
            p2b = fmaf(hb.z, vb.z, p2b); p2b = fmaf(hb.w, vb.w, p2b);
        }
        g_P1[(size_t)bx * H + t] = p1a + p1b;
        g_P2[(size_t)bx * H + t] = p2a + p2b;
    }
}

// ---------------------------------------------------------------------------
// Kernel B: final. 32 molecules per warp iteration.
//   Phase 1 (lane = molecule): coalesced first/z loads, per-lane dist.
//   Phase 2 (j-loop): broadcast (z1|z2<<16, d), cooperative 192-col relu-dot
//   with 32-bit byte-offset addressing, 5-shfl reduce.
// ---------------------------------------------------------------------------
__global__ __launch_bounds__(256, 5)
void final_kernel(const int* __restrict__ z, const float* __restrict__ pos,
                  const float* __restrict__ W2, const float* __restrict__ b2,
                  float* __restrict__ out, int B)
{
    const int tid = threadIdx.x;
    const int wid = tid >> 5, lane = tid & 31;

    // per-lane constants: columns {2*lane + 64j, +1}
    float2 uu[3], vv[3], ww[3];
#pragma unroll
    for (int j = 0; j < 3; j++) {
        int c = 2 * lane + 64 * j;
        uu[j] = *(const float2*)(g_u + c);
        vv[j] = *(const float2*)(g_v + c);
        ww[j] = *(const float2*)(W2 + c);
    }
    const float b2v = b2[0];
    const char* P1b = (const char*)g_P1;
    const char* P2b = (const char*)g_P2;

    const int warpsTotal = gridDim.x * 8;
    for (int base = (blockIdx.x * 8 + wid) * 32; base < B; base += warpsTotal * 32) {
        // ---- phase 1: lane-parallel scalars ----
        const int m = base + lane;
        int zz = 0;
        float d = 0.f;
        if (m < B) {
            int f  = __ldg(g_first + m);
            int nf = __ldg(g_first + m + 1);
            bool has2 = (nf - f) > 1;
            int si = has2 ? f + 1 : f;
            zz = __ldg(z + f) | (__ldg(z + si) << 16);
            float ax = pos[3 * f]     - pos[3 * si];
            float ay = pos[3 * f + 1] - pos[3 * si + 1];
            float az = pos[3 * f + 2] - pos[3 * si + 2];
            d = has2 ? sqrtf(ax * ax + ay * ay + az * az + 1e-12f) : 0.f;
        }
        const int cnt = min(32, B - base);

        // ---- phase 2: cooperative relu-dot per molecule ----
        for (int j = 0; j < cnt; j++) {
            const int   zzj = __shfl_sync(0xffffffffu, zz, j);
            const float dj  = __shfl_sync(0xffffffffu, d, j);
            const uint32_t o1 = (uint32_t)(zzj & 0xffff) * (H * 4u) + lane * 8u;
            const uint32_t o2 = (uint32_t)(zzj >> 16)    * (H * 4u) + lane * 8u;
            float2 a0 = __ldg((const float2*)(P1b + o1));
            float2 a1 = __ldg((const float2*)(P1b + o1 + 256));
            float2 a2 = __ldg((const float2*)(P1b + o1 + 512));
            float2 c0 = __ldg((const float2*)(P2b + o2));
            float2 c1 = __ldg((const float2*)(P2b + o2 + 256));
            float2 c2 = __ldg((const float2*)(P2b + o2 + 512));

            float s;
            {
                float x0 = a0.x + c0.x + fmaf(dj, uu[0].x, vv[0].x);
                float x1 = a0.y + c0.y + fmaf(dj, uu[0].y, vv[0].y);
                s  = fmaxf(x0, 0.f) * ww[0].x;
                s  = fmaf(fmaxf(x1, 0.f), ww[0].y, s);
                x0 = a1.x + c1.x + fmaf(dj, uu[1].x, vv[1].x);
                x1 = a1.y + c1.y + fmaf(dj, uu[1].y, vv[1].y);
                s  = fmaf(fmaxf(x0, 0.f), ww[1].x, s);
                s  = fmaf(fmaxf(x1, 0.f), ww[1].y, s);
                x0 = a2.x + c2.x + fmaf(dj, uu[2].x, vv[2].x);
                x1 = a2.y + c2.y + fmaf(dj, uu[2].y, vv[2].y);
                s  = fmaf(fmaxf(x0, 0.f), ww[2].x, s);
                s  = fmaf(fmaxf(x1, 0.f), ww[2].y, s);
            }
#pragma unroll
            for (int o = 16; o > 0; o >>= 1)
                s += __shfl_xor_sync(0xffffffffu, s, o);
            if (lane == 0) out[base + j] = s + b2v;
        }
    }
}

// ---------------------------------------------------------------------------
extern "C" void kernel_launch(void* const* d_in, const int* in_sizes, int n_in,
                              void* d_out, int out_size)
{
    const int*   z        = (const int*)  d_in[1];
    const float* pos      = (const float*)d_in[2];
    const int*   batch    = (const int*)  d_in[3];
    const float* emb      = (const float*)d_in[5];
    const float* layer_W  = (const float*)d_in[6];
    const float* layer_b  = (const float*)d_in[7];
    const float* layer_g  = (const float*)d_in[8];
    const float* layer_bt = (const float*)d_in[9];
    const float* dist_W   = (const float*)d_in[10];
    const float* dist_b   = (const float*)d_in[11];
    const float* head_W1  = (const float*)d_in[12];
    const float* head_b1  = (const float*)d_in[13];
    const float* head_W2  = (const float*)d_in[14];
    const float* head_b2  = (const float*)d_in[15];
    float* out = (float*)d_out;

    const int B  = out_size;                 // molecules
    const int N  = in_sizes[1];              // atoms
    const int nz = in_sizes[5] / H;          // embedding rows (104)
    const int L  = in_sizes[6] / (H * H);    // layers (5)

    const int gridA = nz + 1 + (N + 255) / 256;
    prep_kernel<<<gridA, 256>>>(batch, N, B, emb, layer_W, layer_b, layer_g,
                                layer_bt, head_W1, dist_W, dist_b, head_b1,
                                L, nz);

    final_kernel<<<148 * 5, 256>>>(z, pos, head_W2, head_b2, out, B);
}

// round 13
// speedup vs baseline: 42.1296x; 1.0095x over previous
#include <cuda_runtime.h>
#include <math.h>
#include <stdint.h>

#define H 192
#define MAXB 200000
#define MAXZ 8192
#define EPSLN 1e-5f

// ===== device scratch (static, no runtime allocation) =====
__device__ int   g_first[MAXB + 1];
__device__ float g_P1[MAXZ * H];
__device__ float g_P2[MAXZ * H];
__device__ float g_u[H];
__device__ float g_v[H];

// ---------------------------------------------------------------------------
// Kernel A: heterogeneous grid.
//   block <  nz : full tower (L layers) for z-row `block` + P1/P2 rows
//   block == nz : u/v vectors
//   block >  nz : findfirst scan chunk (int4, 4 atoms per thread)
// ---------------------------------------------------------------------------
__global__ __launch_bounds__(256)
void prep_kernel(const int* __restrict__ batch, int N, int B,
                 const float* __restrict__ emb,
                 const float* __restrict__ layer_W,
                 const float* __restrict__ layer_b,
                 const float* __restrict__ layer_g,
                 const float* __restrict__ layer_bt,
                 const float* __restrict__ head_W1,
                 const float* __restrict__ dW, const float* __restrict__ dB,
                 const float* __restrict__ b1,
                 int L, int nz)
{
    const int tid = threadIdx.x;
    const int bx  = blockIdx.x;

    if (bx > nz) {
        // ---- findfirst, vectorized: thread handles atoms [i0, i0+4) ----
        int i0 = ((bx - nz - 1) * 256 + tid) * 4;
        if (i0 == 0) g_first[B] = N;          // sentinel
        if (i0 >= N) return;
        int4 b4;
        if (i0 + 3 < N) {
            b4 = *(const int4*)(batch + i0);
        } else {
            b4.x = batch[i0];
            b4.y = (i0 + 1 < N) ? batch[i0 + 1] : b4.x;
            b4.z = (i0 + 2 < N) ? batch[i0 + 2] : b4.y;
            b4.w = (i0 + 3 < N) ? batch[i0 + 3] : b4.z;
        }
        int prev = (i0 == 0) ? -1 : batch[i0 - 1];
        if (b4.x != prev) g_first[b4.x] = i0;
        if (i0 + 1 < N && b4.y != b4.x) g_first[b4.y] = i0 + 1;
        if (i0 + 2 < N && b4.z != b4.y) g_first[b4.z] = i0 + 2;
        if (i0 + 3 < N && b4.w != b4.z) g_first[b4.w] = i0 + 3;
        return;
    }

    if (bx == nz) {
        // ---- u/v ----
        __shared__ float sw[H], sb2[H];
        if (tid < H) { sw[tid] = dW[tid]; sb2[tid] = dB[tid]; }
        __syncthreads();
        if (tid < H) {
            const float* wr = head_W1 + (size_t)tid * 3 * H + 2 * H;
            float au = 0.f, av = 0.f;
#pragma unroll 4
            for (int k = 0; k < H; k++) {
                float w = wr[k];
                au = fmaf(w, sw[k], au);
                av = fmaf(w, sb2[k], av);
            }
            g_u[tid] = au;
            g_v[tid] = av + b1[tid];
        }
        return;
    }

    // ---- tower for z-row bx ----
    __shared__ float hs[H];
    __shared__ float red_s[6], red_q[6];
    const int t = tid;
    const int wid = t >> 5, lane = t & 31;

    if (t < H) hs[t] = emb[(size_t)bx * H + t];
    __syncthreads();

    for (int l = 0; l < L; l++) {
        float y = 0.f;
        if (t < H) {
            const float4* wr = (const float4*)(layer_W + (size_t)l * H * H + (size_t)t * H);
            const float4* hr = (const float4*)hs;
            float a0 = 0.f, a1 = 0.f, a2 = 0.f, a3 = 0.f;
#pragma unroll
            for (int k = 0; k < 48; k += 4) {
                float4 w0 = wr[k],     h0 = hr[k];
                float4 w1 = wr[k + 1], h1 = hr[k + 1];
                float4 w2 = wr[k + 2], h2 = hr[k + 2];
                float4 w3 = wr[k + 3], h3 = hr[k + 3];
                a0 = fmaf(h0.x, w0.x, a0); a0 = fmaf(h0.y, w0.y, a0);
                a0 = fmaf(h0.z, w0.z, a0); a0 = fmaf(h0.w, w0.w, a0);
                a1 = fmaf(h1.x, w1.x, a1); a1 = fmaf(h1.y, w1.y, a1);
                a1 = fmaf(h1.z, w1.z, a1); a1 = fmaf(h1.w, w1.w, a1);
                a2 = fmaf(h2.x, w2.x, a2); a2 = fmaf(h2.y, w2.y, a2);
                a2 = fmaf(h2.z, w2.z, a2); a2 = fmaf(h2.w, w2.w, a2);
                a3 = fmaf(h3.x, w3.x, a3); a3 = fmaf(h3.y, w3.y, a3);
                a3 = fmaf(h3.z, w3.z, a3); a3 = fmaf(h3.w, w3.w, a3);
            }
            y = (a0 + a1) + (a2 + a3) + layer_b[l * H + t];
        }
        float s = y, q = y * y;
#pragma unroll
        for (int o = 16; o > 0; o >>= 1) {
            s += __shfl_xor_sync(0xffffffffu, s, o);
            q += __shfl_xor_sync(0xffffffffu, q, o);
        }
        if (lane == 0 && wid < 6) { red_s[wid] = s; red_q[wid] = q; }
        __syncthreads();
        float S = red_s[0] + red_s[1] + red_s[2] + red_s[3] + red_s[4] + red_s[5];
        float Q = red_q[0] + red_q[1] + red_q[2] + red_q[3] + red_q[4] + red_q[5];
        float mu = S * (1.f / 192.f);
        float var = Q * (1.f / 192.f) - mu * mu;
        float rstd = rsqrtf(fmaxf(var, 0.f) + EPSLN);

        float hnew = 0.f;
        if (t < H) {
            float v = fmaxf((y - mu) * rstd * layer_g[l * H + t] + layer_bt[l * H + t], 0.f);
            hnew = hs[t] + v;
        }
        __syncthreads();
        if (t < H) hs[t] = hnew;
        __syncthreads();
    }

    if (t < H) {
        const float4* w1 = (const float4*)(head_W1 + (size_t)t * 3 * H);
        const float4* w2 = (const float4*)(head_W1 + (size_t)t * 3 * H + H);
        const float4* hr = (const float4*)hs;
        float p1a = 0.f, p1b = 0.f, p2a = 0.f, p2b = 0.f;
#pragma unroll
        for (int k = 0; k < 48; k += 2) {
            float4 ha = hr[k], hb = hr[k + 1];
            float4 wa = w1[k], wb = w1[k + 1];
            p1a = fmaf(ha.x, wa.x, p1a); p1a = fmaf(ha.y, wa.y, p1a);
            p1a = fmaf(ha.z, wa.z, p1a); p1a = fmaf(ha.w, wa.w, p1a);
            p1b = fmaf(hb.x, wb.x, p1b); p1b = fmaf(hb.y, wb.y, p1b);
            p1b = fmaf(hb.z, wb.z, p1b); p1b = fmaf(hb.w, wb.w, p1b);
            float4 va = w2[k], vb = w2[k + 1];
            p2a = fmaf(ha.x, va.x, p2a); p2a = fmaf(ha.y, va.y, p2a);
            p2a = fmaf(ha.z, va.z, p2a); p2a = fmaf(ha.w, va.w, p2a);
            p2b = fmaf(hb.x, vb.x, p2b); p2b = fmaf(hb.y, vb.y, p2b);
            p2b = fmaf(hb.z, vb.z, p2b); p2b = fmaf(hb.w, vb.w, p2b);
        }
        g_P1[(size_t)bx * H + t] = p1a + p1b;
        g_P2[(size_t)bx * H + t] = p2a + p2b;
    }
}

// ---------------------------------------------------------------------------
// Kernel B: final. Balanced contiguous per-warp ranges; 32 molecules per
// inner batch (phase 1 lane-parallel scalars, phase 2 cooperative relu-dot).
// ---------------------------------------------------------------------------
__global__ __launch_bounds__(256, 5)
void final_kernel(const int* __restrict__ z, const float* __restrict__ pos,
                  const float* __restrict__ W2, const float* __restrict__ b2,
                  float* __restrict__ out, int B)
{
    const int tid = threadIdx.x;
    const int wid = tid >> 5, lane = tid & 31;

    // per-lane constants: columns {2*lane + 64j, +1}
    float2 uu[3], vv[3], ww[3];
#pragma unroll
    for (int j = 0; j < 3; j++) {
        int c = 2 * lane + 64 * j;
        uu[j] = *(const float2*)(g_u + c);
        vv[j] = *(const float2*)(g_v + c);
        ww[j] = *(const float2*)(W2 + c);
    }
    const float b2v = b2[0];
    const char* P1b = (const char*)g_P1;
    const char* P2b = (const char*)g_P2;

    // balanced contiguous range per warp
    const int warpsTotal = gridDim.x * 8;
    const int gwarp = blockIdx.x * 8 + wid;
    const int per = (B + warpsTotal - 1) / warpsTotal;
    const int m0 = gwarp * per;
    const int m1 = min(B, m0 + per);

    for (int base = m0; base < m1; base += 32) {
        const int cnt = min(32, m1 - base);
        // ---- phase 1: lane-parallel scalars ----
        int zz = 0;
        float d = 0.f;
        if (lane < cnt) {
            const int m = base + lane;
            int f  = __ldg(g_first + m);
            int nf = __ldg(g_first + m + 1);
            bool has2 = (nf - f) > 1;
            int si = has2 ? f + 1 : f;
            zz = __ldg(z + f) | (__ldg(z + si) << 16);
            float ax = pos[3 * f]     - pos[3 * si];
            float ay = pos[3 * f + 1] - pos[3 * si + 1];
            float az = pos[3 * f + 2] - pos[3 * si + 2];
            d = has2 ? sqrtf(ax * ax + ay * ay + az * az + 1e-12f) : 0.f;
        }

        // ---- phase 2: cooperative relu-dot per molecule ----
        for (int j = 0; j < cnt; j++) {
            const int   zzj = __shfl_sync(0xffffffffu, zz, j);
            const float dj  = __shfl_sync(0xffffffffu, d, j);
            const uint32_t o1 = (uint32_t)(zzj & 0xffff) * (H * 4u) + lane * 8u;
            const uint32_t o2 = (uint32_t)(zzj >> 16)    * (H * 4u) + lane * 8u;
            float2 a0 = __ldg((const float2*)(P1b + o1));
            float2 a1 = __ldg((const float2*)(P1b + o1 + 256));
            float2 a2 = __ldg((const float2*)(P1b + o1 + 512));
            float2 c0 = __ldg((const float2*)(P2b + o2));
            float2 c1 = __ldg((const float2*)(P2b + o2 + 256));
            float2 c2 = __ldg((const float2*)(P2b + o2 + 512));

            float s;
            {
                float x0 = a0.x + c0.x + fmaf(dj, uu[0].x, vv[0].x);
                float x1 = a0.y + c0.y + fmaf(dj, uu[0].y, vv[0].y);
                s  = fmaxf(x0, 0.f) * ww[0].x;
                s  = fmaf(fmaxf(x1, 0.f), ww[0].y, s);
                x0 = a1.x + c1.x + fmaf(dj, uu[1].x, vv[1].x);
                x1 = a1.y + c1.y + fmaf(dj, uu[1].y, vv[1].y);
                s  = fmaf(fmaxf(x0, 0.f), ww[1].x, s);
                s  = fmaf(fmaxf(x1, 0.f), ww[1].y, s);
                x0 = a2.x + c2.x + fmaf(dj, uu[2].x, vv[2].x);
                x1 = a2.y + c2.y + fmaf(dj, uu[2].y, vv[2].y);
                s  = fmaf(fmaxf(x0, 0.f), ww[2].x, s);
                s  = fmaf(fmaxf(x1, 0.f), ww[2].y, s);
            }
#pragma unroll
            for (int o = 16; o > 0; o >>= 1)
                s += __shfl_xor_sync(0xffffffffu, s, o);
            if (lane == 0) out[base + j] = s + b2v;
        }
    }
}

// ---------------------------------------------------------------------------
extern "C" void kernel_launch(void* const* d_in, const int* in_sizes, int n_in,
                              void* d_out, int out_size)
{
    const int*   z        = (const int*)  d_in[1];
    const float* pos      = (const float*)d_in[2];
    const int*   batch    = (const int*)  d_in[3];
    const float* emb      = (const float*)d_in[5];
    const float* layer_W  = (const float*)d_in[6];
    const float* layer_b  = (const float*)d_in[7];
    const float* layer_g  = (const float*)d_in[8];
    const float* layer_bt = (const float*)d_in[9];
    const float* dist_W   = (const float*)d_in[10];
    const float* dist_b   = (const float*)d_in[11];
    const float* head_W1  = (const float*)d_in[12];
    const float* head_b1  = (const float*)d_in[13];
    const float* head_W2  = (const float*)d_in[14];
    const float* head_b2  = (const float*)d_in[15];
    float* out = (float*)d_out;

    const int B  = out_size;                 // molecules
    const int N  = in_sizes[1];              // atoms
    const int nz = in_sizes[5] / H;          // embedding rows (104)
    const int L  = in_sizes[6] / (H * H);    // layers (5)

    const int gridA = nz + 1 + (N + 1023) / 1024;
    prep_kernel<<<gridA, 256>>>(batch, N, B, emb, layer_W, layer_b, layer_g,
                                layer_bt, head_W1, dist_W, dist_b, head_b1,
                                L, nz);

    final_kernel<<<148 * 5, 256>>>(z, pos, head_W2, head_b2, out, B);
}